// round 7
// baseline (speedup 1.0000x reference)
#include <cuda_runtime.h>
#include <cuda_bf16.h>
#include <cstdint>

#define NB 4
#define NS 2048
#define NE 1024
#define NH 16
#define ND 64
#define AST 65

// ======================= scratch (allocation-free) =========================
__device__ float g_q[(size_t)NB * NH * NS * ND];
__device__ float g_k[(size_t)NB * NH * NS * ND];
__device__ float g_v[(size_t)NB * NH * NS * ND];
__device__ __nv_bfloat16 g_xh[(size_t)NB * NS * NE];
__device__ __nv_bfloat16 g_xl[(size_t)NB * NS * NE];
__device__ __nv_bfloat16 g_ah[(size_t)NB * NS * NE];
__device__ __nv_bfloat16 g_al[(size_t)NB * NS * NE];
__device__ __nv_bfloat16 g_wqh[(size_t)NE * NE];
__device__ __nv_bfloat16 g_wql[(size_t)NE * NE];
__device__ __nv_bfloat16 g_wkh[(size_t)NE * NE];
__device__ __nv_bfloat16 g_wkl[(size_t)NE * NE];
__device__ __nv_bfloat16 g_wvh[(size_t)NE * NE];
__device__ __nv_bfloat16 g_wvl[(size_t)NE * NE];
__device__ __nv_bfloat16 g_woh[(size_t)NE * NE];
__device__ __nv_bfloat16 g_wol[(size_t)NE * NE];

// ======================= warp-level MMA helpers ============================
__device__ __forceinline__ uint32_t smem_u32(const void* p) {
    uint32_t a;
    asm("{ .reg .u64 t; cvta.to.shared.u64 t, %1; cvt.u32.u64 %0, t; }"
        : "=r"(a) : "l"(p));
    return a;
}
__device__ __forceinline__ void ldm_x4(uint32_t addr, uint32_t* r) {
    asm volatile("ldmatrix.sync.aligned.m8n8.x4.shared.b16 {%0,%1,%2,%3}, [%4];"
                 : "=r"(r[0]), "=r"(r[1]), "=r"(r[2]), "=r"(r[3]) : "r"(addr));
}
__device__ __forceinline__ void mma_bf16(float* d, const uint32_t* a,
                                         const uint32_t* b) {
    asm volatile(
        "mma.sync.aligned.m16n8k16.row.col.f32.bf16.bf16.f32 "
        "{%0,%1,%2,%3}, {%4,%5,%6,%7}, {%8,%9}, {%0,%1,%2,%3};"
        : "+f"(d[0]), "+f"(d[1]), "+f"(d[2]), "+f"(d[3])
        : "r"(a[0]), "r"(a[1]), "r"(a[2]), "r"(a[3]), "r"(b[0]), "r"(b[1]));
}
#define CP_ASYNC16(dst, src)                                                   \
    asm volatile("cp.async.ca.shared.global [%0], [%1], 16;"                   \
                 :: "r"(dst), "l"(src) : "memory")
#define CP_COMMIT() asm volatile("cp.async.commit_group;" ::: "memory")
#define CP_WAIT1()  asm volatile("cp.async.wait_group 1;" ::: "memory")
#define CP_WAIT0()  asm volatile("cp.async.wait_group 0;" ::: "memory")

// ======================= fp32 -> bf16 hi/lo split ==========================
__global__ void __launch_bounds__(256)
cvt_split(const float* __restrict__ src, __nv_bfloat16* __restrict__ hi,
          __nv_bfloat16* __restrict__ lo, int n4) {
    int i = blockIdx.x * 256 + threadIdx.x;
    if (i >= n4) return;
    float4 v = reinterpret_cast<const float4*>(src)[i];
    __nv_bfloat16 h0 = __float2bfloat16(v.x);
    __nv_bfloat16 h1 = __float2bfloat16(v.y);
    __nv_bfloat16 h2 = __float2bfloat16(v.z);
    __nv_bfloat16 h3 = __float2bfloat16(v.w);
    __nv_bfloat16 l0 = __float2bfloat16(v.x - __bfloat162float(h0));
    __nv_bfloat16 l1 = __float2bfloat16(v.y - __bfloat162float(h1));
    __nv_bfloat16 l2 = __float2bfloat16(v.z - __bfloat162float(h2));
    __nv_bfloat16 l3 = __float2bfloat16(v.w - __bfloat162float(h3));
    reinterpret_cast<__nv_bfloat162*>(hi)[2 * i]     = __halves2bfloat162(h0, h1);
    reinterpret_cast<__nv_bfloat162*>(hi)[2 * i + 1] = __halves2bfloat162(h2, h3);
    reinterpret_cast<__nv_bfloat162*>(lo)[2 * i]     = __halves2bfloat162(l0, l1);
    reinterpret_cast<__nv_bfloat162*>(lo)[2 * i + 1] = __halves2bfloat162(l2, l3);
}

// ======================= bf16-split GEMM via mma.sync ======================
// C[M,128cols/blk] = A @ W^T; D = Ah*Wh + Ah*Wl + Al*Wh  (fp32 accum).
// CTA 128x128, 8 warps (4m x 2n), warp tile 32x64.
// K-chunk 32, double-buffered cp.async pipeline.
#define GT_STRIDE 40                       // bf16 elems per smem row (80 B)
#define GT_TILE_B (128 * GT_STRIDE * 2)    // 10240 B per tile
#define GT_BUF_B (4 * GT_TILE_B)           // Ah, Al, Bh, Bl
#define GT_TOTAL (2 * GT_BUF_B)            // 81920 B

template <int SCATTER>
__global__ void __launch_bounds__(256)
gemm_mma(const __nv_bfloat16* __restrict__ Ah, const __nv_bfloat16* __restrict__ Al,
         const __nv_bfloat16* __restrict__ Bh, const __nv_bfloat16* __restrict__ Bl,
         float* __restrict__ C) {
    extern __shared__ __align__(128) char smem[];
    const uint32_t sb = smem_u32(smem);
    const int tid = threadIdx.x;
    const int wid = tid >> 5, lane = tid & 31;
    const int wm = wid & 3, wn = wid >> 2;
    const size_t m0 = (size_t)blockIdx.y * 128;
    const size_t n0 = (size_t)blockIdx.x * 128;

    const __nv_bfloat16* srcs[4] = {Ah, Al, Bh, Bl};

    // ---- async chunk loader: 4 tiles x 128 rows x 64B ----
    auto issue_chunk = [&](int c, int buf) {
        const int kofs = c * 32;
        const uint32_t base = sb + buf * GT_BUF_B;
#pragma unroll
        for (int it = 0; it < 8; it++) {
            const int t = it >> 1;  // tile index (const per unrolled iter)
            const int s = tid + it * 256;
            const int r = (s >> 2) & 127;
            const int g = s & 3;
            const size_t row = (t < 2 ? m0 : n0) + r;
            const __nv_bfloat16* gsrc = srcs[t] + row * NE + kofs + g * 8;
            const uint32_t dst = base + t * GT_TILE_B + r * (GT_STRIDE * 2) + g * 16;
            CP_ASYNC16(dst, gsrc);
        }
        CP_COMMIT();
    };

    float acc[2][8][4];
#pragma unroll
    for (int mi = 0; mi < 2; mi++)
#pragma unroll
        for (int nj = 0; nj < 8; nj++)
#pragma unroll
            for (int e = 0; e < 4; e++) acc[mi][nj][e] = 0.f;

    // ldmatrix lane addressing
    const int a_row = wm * 32 + (lane & 15);
    const int a_kb  = (lane >> 4) * 16;
    const int b_row = wn * 64 + (lane >> 4) * 8 + (lane & 7);
    const int b_kb  = ((lane >> 3) & 1) * 16;

    issue_chunk(0, 0);
    for (int c = 0; c < 32; c++) {
        const int buf = c & 1;
        if (c + 1 < 32) { issue_chunk(c + 1, buf ^ 1); CP_WAIT1(); }
        else            { CP_WAIT0(); }
        __syncthreads();

        const uint32_t ahb = sb + buf * GT_BUF_B;
        const uint32_t alb = ahb + GT_TILE_B;
        const uint32_t bhb = ahb + 2 * GT_TILE_B;
        const uint32_t blb = ahb + 3 * GT_TILE_B;

#pragma unroll
        for (int kk = 0; kk < 2; kk++) {
            const int kbyte = kk * 32;
            uint32_t afh[2][4], afl[2][4], bfh[4][4], bfl[4][4];
#pragma unroll
            for (int mi = 0; mi < 2; mi++) {
                ldm_x4(ahb + (a_row + mi * 16) * (GT_STRIDE * 2) + kbyte + a_kb,
                       afh[mi]);
                ldm_x4(alb + (a_row + mi * 16) * (GT_STRIDE * 2) + kbyte + a_kb,
                       afl[mi]);
            }
#pragma unroll
            for (int j = 0; j < 4; j++) {
                ldm_x4(bhb + (b_row + j * 16) * (GT_STRIDE * 2) + kbyte + b_kb,
                       bfh[j]);
                ldm_x4(blb + (b_row + j * 16) * (GT_STRIDE * 2) + kbyte + b_kb,
                       bfl[j]);
            }
#pragma unroll
            for (int mi = 0; mi < 2; mi++)
#pragma unroll
                for (int j = 0; j < 4; j++) {
                    // frag 2j   -> regs {b[0], b[1]},  frag 2j+1 -> {b[2], b[3]}
                    mma_bf16(acc[mi][2 * j],     afh[mi], bfh[j]);
                    mma_bf16(acc[mi][2 * j + 1], afh[mi], bfh[j] + 2);
                    mma_bf16(acc[mi][2 * j],     afh[mi], bfl[j]);
                    mma_bf16(acc[mi][2 * j + 1], afh[mi], bfl[j] + 2);
                    mma_bf16(acc[mi][2 * j],     afl[mi], bfh[j]);
                    mma_bf16(acc[mi][2 * j + 1], afl[mi], bfh[j] + 2);
                }
        }
        __syncthreads();
    }

    // ---- epilogue ----
    const int row_in = lane >> 2;
    const int col2 = 2 * (lane & 3);
#pragma unroll
    for (int mi = 0; mi < 2; mi++) {
#pragma unroll
        for (int h8 = 0; h8 < 2; h8++) {
            const size_t m = m0 + wm * 32 + mi * 16 + row_in + h8 * 8;
            float* dst;
            if (SCATTER == 0) {
                dst = C + m * NE + n0 + wn * 64;
            } else {
                const size_t hh = (n0 + wn * 64) / ND;
                const size_t bbi = m / NS, ss = m % NS;
                dst = C + ((bbi * NH + hh) * NS + ss) * ND;
            }
#pragma unroll
            for (int nj = 0; nj < 8; nj++) {
                float2 v = h8 ? make_float2(acc[mi][nj][2], acc[mi][nj][3])
                              : make_float2(acc[mi][nj][0], acc[mi][nj][1]);
                *reinterpret_cast<float2*>(dst + nj * 8 + col2) = v;
            }
        }
    }
}

// ======================= flash attention (fp32) ============================
__global__ void __launch_bounds__(256)
attn_kernel(const float* __restrict__ Q, const float* __restrict__ K,
            const float* __restrict__ V, const int* __restrict__ amask,
            __nv_bfloat16* __restrict__ Oh, __nv_bfloat16* __restrict__ Ol) {
    extern __shared__ float sm[];
    float* Qs = sm;
    float* Ks = sm + 64 * AST;
    float* Vs = sm + 2 * 64 * AST;
    float* Ps = sm + 3 * 64 * AST;

    const int tid = threadIdx.x;
    const int tx = tid & 15;
    const int ty = tid >> 4;
    const int qt = blockIdx.x;
    const int q0 = qt * 64;
    const int bh = blockIdx.y;
    const int b = bh / NH;
    const int h = bh % NH;

    const float* qbase = Q + (size_t)bh * NS * ND;
    const float* kbase = K + (size_t)bh * NS * ND;
    const float* vbase = V + (size_t)bh * NS * ND;

    for (int f = tid; f < 64 * 16; f += 256) {
        int r = f >> 4, cc = (f & 15) << 2;
        float4 v4 = *(const float4*)(qbase + (size_t)(q0 + r) * ND + cc);
        Qs[r * AST + cc + 0] = v4.x; Qs[r * AST + cc + 1] = v4.y;
        Qs[r * AST + cc + 2] = v4.z; Qs[r * AST + cc + 3] = v4.w;
    }

    float acco[4][4], rm[4], rl[4];
#pragma unroll
    for (int i = 0; i < 4; i++) {
        rm[i] = -1e30f; rl[i] = 0.f;
#pragma unroll
        for (int j = 0; j < 4; j++) acco[i][j] = 0.f;
    }
    const float scale = 0.125f;

    for (int kt = 0; kt <= qt; kt++) {
        const int k0 = kt * 64;
        __syncthreads();
        for (int f = tid; f < 64 * 16; f += 256) {
            int r = f >> 4, cc = (f & 15) << 2;
            float4 kv = *(const float4*)(kbase + (size_t)(k0 + r) * ND + cc);
            Ks[r * AST + cc + 0] = kv.x; Ks[r * AST + cc + 1] = kv.y;
            Ks[r * AST + cc + 2] = kv.z; Ks[r * AST + cc + 3] = kv.w;
            float4 vv = *(const float4*)(vbase + (size_t)(k0 + r) * ND + cc);
            Vs[r * AST + cc + 0] = vv.x; Vs[r * AST + cc + 1] = vv.y;
            Vs[r * AST + cc + 2] = vv.z; Vs[r * AST + cc + 3] = vv.w;
        }
        __syncthreads();

        float sacc[4][4];
#pragma unroll
        for (int i = 0; i < 4; i++)
#pragma unroll
            for (int j = 0; j < 4; j++) sacc[i][j] = 0.f;

#pragma unroll 16
        for (int d = 0; d < 64; d++) {
            float a[4], bq[4];
#pragma unroll
            for (int i = 0; i < 4; i++) a[i] = Qs[(4 * ty + i) * AST + d];
#pragma unroll
            for (int j = 0; j < 4; j++) bq[j] = Ks[(4 * tx + j) * AST + d];
#pragma unroll
            for (int i = 0; i < 4; i++)
#pragma unroll
                for (int j = 0; j < 4; j++)
                    sacc[i][j] = fmaf(a[i], bq[j], sacc[i][j]);
        }

        int pmv[4];
#pragma unroll
        for (int j = 0; j < 4; j++) pmv[j] = amask[b * NS + k0 + 4 * tx + j];
        const bool diag = (kt == qt);
#pragma unroll
        for (int i = 0; i < 4; i++) {
            int qi = q0 + 4 * ty + i;
#pragma unroll
            for (int j = 0; j < 4; j++) {
                int kj = k0 + 4 * tx + j;
                float s = sacc[i][j] * scale;
                if ((diag && kj > qi) || pmv[j] == 0) s = -1e30f;
                sacc[i][j] = s;
            }
        }

#pragma unroll
        for (int i = 0; i < 4; i++) {
            float mt = fmaxf(fmaxf(sacc[i][0], sacc[i][1]),
                             fmaxf(sacc[i][2], sacc[i][3]));
            mt = fmaxf(mt, __shfl_xor_sync(0xffffffffu, mt, 8));
            mt = fmaxf(mt, __shfl_xor_sync(0xffffffffu, mt, 4));
            mt = fmaxf(mt, __shfl_xor_sync(0xffffffffu, mt, 2));
            mt = fmaxf(mt, __shfl_xor_sync(0xffffffffu, mt, 1));
            float mnew = fmaxf(rm[i], mt);
            float fac = __expf(rm[i] - mnew);
            rm[i] = mnew;
            float psum = 0.f;
#pragma unroll
            for (int j = 0; j < 4; j++) {
                float p = __expf(sacc[i][j] - mnew);
                Ps[(4 * ty + i) * AST + 4 * tx + j] = p;
                psum += p;
            }
            psum += __shfl_xor_sync(0xffffffffu, psum, 8);
            psum += __shfl_xor_sync(0xffffffffu, psum, 4);
            psum += __shfl_xor_sync(0xffffffffu, psum, 2);
            psum += __shfl_xor_sync(0xffffffffu, psum, 1);
            rl[i] = rl[i] * fac + psum;
#pragma unroll
            for (int j = 0; j < 4; j++) acco[i][j] *= fac;
        }
        __syncthreads();

#pragma unroll 16
        for (int j = 0; j < 64; j++) {
            float a[4], vv[4];
#pragma unroll
            for (int i = 0; i < 4; i++) a[i] = Ps[(4 * ty + i) * AST + j];
#pragma unroll
            for (int jj = 0; jj < 4; jj++) vv[jj] = Vs[j * AST + 4 * tx + jj];
#pragma unroll
            for (int i = 0; i < 4; i++)
#pragma unroll
                for (int jj = 0; jj < 4; jj++)
                    acco[i][jj] = fmaf(a[i], vv[jj], acco[i][jj]);
        }
    }

    // epilogue: write bf16 hi/lo split of [B,S,E]
#pragma unroll
    for (int i = 0; i < 4; i++) {
        float inv = 1.f / rl[i];
        size_t base = ((size_t)(b * NS + q0 + 4 * ty + i)) * NE + h * ND + 4 * tx;
        float v0 = acco[i][0] * inv, v1 = acco[i][1] * inv;
        float v2 = acco[i][2] * inv, v3 = acco[i][3] * inv;
        __nv_bfloat16 h0 = __float2bfloat16(v0), h1 = __float2bfloat16(v1);
        __nv_bfloat16 h2 = __float2bfloat16(v2), h3 = __float2bfloat16(v3);
        __nv_bfloat16 l0 = __float2bfloat16(v0 - __bfloat162float(h0));
        __nv_bfloat16 l1 = __float2bfloat16(v1 - __bfloat162float(h1));
        __nv_bfloat16 l2 = __float2bfloat16(v2 - __bfloat162float(h2));
        __nv_bfloat16 l3 = __float2bfloat16(v3 - __bfloat162float(h3));
        *reinterpret_cast<__nv_bfloat162*>(Oh + base)     = __halves2bfloat162(h0, h1);
        *reinterpret_cast<__nv_bfloat162*>(Oh + base + 2) = __halves2bfloat162(h2, h3);
        *reinterpret_cast<__nv_bfloat162*>(Ol + base)     = __halves2bfloat162(l0, l1);
        *reinterpret_cast<__nv_bfloat162*>(Ol + base + 2) = __halves2bfloat162(l2, l3);
    }
}

// ======================= launcher ==========================================
extern "C" void kernel_launch(void* const* d_in, const int* in_sizes, int n_in,
                              void* d_out, int out_size) {
    (void)in_sizes; (void)n_in; (void)out_size;
    const float* x  = (const float*)d_in[0];
    const int*   am = (const int*)d_in[1];
    const float* wq = (const float*)d_in[2];
    const float* wk = (const float*)d_in[3];
    const float* wv = (const float*)d_in[4];
    const float* wo = (const float*)d_in[5];
    float* out = (float*)d_out;

    float *q, *k, *v;
    __nv_bfloat16 *xh, *xl, *ah, *al;
    __nv_bfloat16 *wqh, *wql, *wkh, *wkl, *wvh, *wvl, *woh, *wol;
    cudaGetSymbolAddress((void**)&q, g_q);
    cudaGetSymbolAddress((void**)&k, g_k);
    cudaGetSymbolAddress((void**)&v, g_v);
    cudaGetSymbolAddress((void**)&xh, g_xh);
    cudaGetSymbolAddress((void**)&xl, g_xl);
    cudaGetSymbolAddress((void**)&ah, g_ah);
    cudaGetSymbolAddress((void**)&al, g_al);
    cudaGetSymbolAddress((void**)&wqh, g_wqh);
    cudaGetSymbolAddress((void**)&wql, g_wql);
    cudaGetSymbolAddress((void**)&wkh, g_wkh);
    cudaGetSymbolAddress((void**)&wkl, g_wkl);
    cudaGetSymbolAddress((void**)&wvh, g_wvh);
    cudaGetSymbolAddress((void**)&wvl, g_wvl);
    cudaGetSymbolAddress((void**)&woh, g_woh);
    cudaGetSymbolAddress((void**)&wol, g_wol);

    const int NX4 = NB * NS * NE / 4, NW4 = NE * NE / 4;
    cvt_split<<<(NX4 + 255) / 256, 256>>>(x, xh, xl, NX4);
    cvt_split<<<(NW4 + 255) / 256, 256>>>(wq, wqh, wql, NW4);
    cvt_split<<<(NW4 + 255) / 256, 256>>>(wk, wkh, wkl, NW4);
    cvt_split<<<(NW4 + 255) / 256, 256>>>(wv, wvh, wvl, NW4);
    cvt_split<<<(NW4 + 255) / 256, 256>>>(wo, woh, wol, NW4);

    cudaFuncSetAttribute(gemm_mma<0>, cudaFuncAttributeMaxDynamicSharedMemorySize, GT_TOTAL);
    cudaFuncSetAttribute(gemm_mma<1>, cudaFuncAttributeMaxDynamicSharedMemorySize, GT_TOTAL);

    const dim3 gg(NE / 128, (NB * NS) / 128);  // (8, 64)
    gemm_mma<1><<<gg, 256, GT_TOTAL>>>(xh, xl, wqh, wql, q);
    gemm_mma<1><<<gg, 256, GT_TOTAL>>>(xh, xl, wkh, wkl, k);
    gemm_mma<1><<<gg, 256, GT_TOTAL>>>(xh, xl, wvh, wvl, v);

    const int ATTN_SMEM = 4 * 64 * AST * (int)sizeof(float);
    cudaFuncSetAttribute(attn_kernel,
                         cudaFuncAttributeMaxDynamicSharedMemorySize, ATTN_SMEM);
    attn_kernel<<<dim3(NS / 64, NB * NH), 256, ATTN_SMEM>>>(q, k, v, am, ah, al);

    gemm_mma<0><<<gg, 256, GT_TOTAL>>>(ah, al, woh, wol, out);
}

// round 8
// speedup vs baseline: 1.8941x; 1.8941x over previous
#include <cuda_runtime.h>
#include <cuda_fp16.h>
#include <cstdint>

#define NB 4
#define NS 2048
#define NE 1024
#define NH 16
#define ND 64
#define AST 65

// ======================= scratch (allocation-free) =========================
__device__ float g_q[(size_t)NB * NH * NS * ND];
__device__ float g_k[(size_t)NB * NH * NS * ND];
__device__ float g_v[(size_t)NB * NH * NS * ND];
__device__ __half g_xh[(size_t)NB * NS * NE];
__device__ __half g_ah[(size_t)NB * NS * NE];
__device__ __half g_wqh[(size_t)NE * NE];
__device__ __half g_wql[(size_t)NE * NE];
__device__ __half g_wkh[(size_t)NE * NE];
__device__ __half g_wkl[(size_t)NE * NE];
__device__ __half g_wvh[(size_t)NE * NE];
__device__ __half g_wvl[(size_t)NE * NE];
__device__ __half g_woh[(size_t)NE * NE];
__device__ __half g_wol[(size_t)NE * NE];

// ======================= warp-level MMA helpers ============================
__device__ __forceinline__ uint32_t smem_u32(const void* p) {
    uint32_t a;
    asm("{ .reg .u64 t; cvta.to.shared.u64 t, %1; cvt.u32.u64 %0, t; }"
        : "=r"(a) : "l"(p));
    return a;
}
__device__ __forceinline__ void ldm_x4(uint32_t addr, uint32_t* r) {
    asm volatile("ldmatrix.sync.aligned.m8n8.x4.shared.b16 {%0,%1,%2,%3}, [%4];"
                 : "=r"(r[0]), "=r"(r[1]), "=r"(r[2]), "=r"(r[3]) : "r"(addr));
}
__device__ __forceinline__ void mma_f16(float* d, const uint32_t* a,
                                        const uint32_t* b) {
    asm volatile(
        "mma.sync.aligned.m16n8k16.row.col.f32.f16.f16.f32 "
        "{%0,%1,%2,%3}, {%4,%5,%6,%7}, {%8,%9}, {%0,%1,%2,%3};"
        : "+f"(d[0]), "+f"(d[1]), "+f"(d[2]), "+f"(d[3])
        : "r"(a[0]), "r"(a[1]), "r"(a[2]), "r"(a[3]), "r"(b[0]), "r"(b[1]));
}
#define CP_ASYNC16(dst, src)                                                   \
    asm volatile("cp.async.ca.shared.global [%0], [%1], 16;"                   \
                 :: "r"(dst), "l"(src) : "memory")
#define CP_COMMIT() asm volatile("cp.async.commit_group;" ::: "memory")
#define CP_WAIT1()  asm volatile("cp.async.wait_group 1;" ::: "memory")
#define CP_WAIT0()  asm volatile("cp.async.wait_group 0;" ::: "memory")

// ======================= conversion kernels ================================
__global__ void __launch_bounds__(256)
cvt_hi(const float* __restrict__ src, __half* __restrict__ hi, int n4) {
    int i = blockIdx.x * 256 + threadIdx.x;
    if (i >= n4) return;
    float4 v = reinterpret_cast<const float4*>(src)[i];
    __half2 p0 = __floats2half2_rn(v.x, v.y);
    __half2 p1 = __floats2half2_rn(v.z, v.w);
    reinterpret_cast<__half2*>(hi)[2 * i]     = p0;
    reinterpret_cast<__half2*>(hi)[2 * i + 1] = p1;
}

__global__ void __launch_bounds__(256)
cvt_split16(const float* __restrict__ src, __half* __restrict__ hi,
            __half* __restrict__ lo, int n4) {
    int i = blockIdx.x * 256 + threadIdx.x;
    if (i >= n4) return;
    float4 v = reinterpret_cast<const float4*>(src)[i];
    __half h0 = __float2half_rn(v.x);
    __half h1 = __float2half_rn(v.y);
    __half h2 = __float2half_rn(v.z);
    __half h3 = __float2half_rn(v.w);
    __half l0 = __float2half_rn(v.x - __half2float(h0));
    __half l1 = __float2half_rn(v.y - __half2float(h1));
    __half l2 = __float2half_rn(v.z - __half2float(h2));
    __half l3 = __float2half_rn(v.w - __half2float(h3));
    reinterpret_cast<__half2*>(hi)[2 * i]     = __halves2half2(h0, h1);
    reinterpret_cast<__half2*>(hi)[2 * i + 1] = __halves2half2(h2, h3);
    reinterpret_cast<__half2*>(lo)[2 * i]     = __halves2half2(l0, l1);
    reinterpret_cast<__half2*>(lo)[2 * i + 1] = __halves2half2(l2, l3);
}

// ======================= fp16 2-pass GEMM via mma.sync =====================
// C[M,N] = A @ W^T;  D = Ah*Wh + Ah*Wl  (fp32 accum).
// CTA 128x128, 8 warps (4m x 2n), warp tile 32x64.
// K-chunk 32, 3-stage cp.async pipeline, 3 smem tiles per stage.
#define GT_STRIDE 40                        // halves per smem row (80 B)
#define GT_TILE_B (128 * GT_STRIDE * 2)     // 10240 B per tile
#define GT_STAGE_B (3 * GT_TILE_B)          // Ah, Wh, Wl = 30720 B
#define GT_TOTAL (3 * GT_STAGE_B)           // 92160 B

template <int SCATTER>
__global__ void __launch_bounds__(256)
gemm_mma(const __half* __restrict__ Ah, const __half* __restrict__ Bh,
         const __half* __restrict__ Bl, float* __restrict__ C) {
    extern __shared__ __align__(128) char smem[];
    const uint32_t sb = smem_u32(smem);
    const int tid = threadIdx.x;
    const int wid = tid >> 5, lane = tid & 31;
    const int wm = wid & 3, wn = wid >> 2;
    const size_t m0 = (size_t)blockIdx.y * 128;
    const size_t n0 = (size_t)blockIdx.x * 128;

    const __half* srcs[3] = {Ah, Bh, Bl};

    auto issue_chunk = [&](int c, int buf) {
        const int kofs = c * 32;
        const uint32_t base = sb + buf * GT_STAGE_B;
#pragma unroll
        for (int it = 0; it < 6; it++) {
            const int t = it >> 1;
            const int s = tid + it * 256;
            const int r = (s >> 2) & 127;
            const int g = s & 3;
            const size_t row = (t == 0 ? m0 : n0) + r;
            const __half* gsrc = srcs[t] + row * NE + kofs + g * 8;
            const uint32_t dst = base + t * GT_TILE_B + r * (GT_STRIDE * 2) + g * 16;
            CP_ASYNC16(dst, gsrc);
        }
        CP_COMMIT();
    };

    float acc[2][8][4];
#pragma unroll
    for (int mi = 0; mi < 2; mi++)
#pragma unroll
        for (int nj = 0; nj < 8; nj++)
#pragma unroll
            for (int e = 0; e < 4; e++) acc[mi][nj][e] = 0.f;

    const int a_row = wm * 32 + (lane & 15);
    const int a_kb  = (lane >> 4) * 16;
    const int b_row = wn * 64 + (lane >> 4) * 8 + (lane & 7);
    const int b_kb  = ((lane >> 3) & 1) * 16;

    issue_chunk(0, 0);
    issue_chunk(1, 1);
    for (int c = 0; c < 32; c++) {
        const int buf = c % 3;
        if (c < 31) CP_WAIT1(); else CP_WAIT0();
        __syncthreads();
        if (c + 2 < 32) issue_chunk(c + 2, (c + 2) % 3);

        const uint32_t ahb = sb + buf * GT_STAGE_B;
        const uint32_t bhb = ahb + GT_TILE_B;
        const uint32_t blb = ahb + 2 * GT_TILE_B;

#pragma unroll
        for (int kk = 0; kk < 2; kk++) {
            const int kbyte = kk * 32;
            uint32_t afh[2][4], bfh[4][4], bfl[4][4];
#pragma unroll
            for (int mi = 0; mi < 2; mi++)
                ldm_x4(ahb + (a_row + mi * 16) * (GT_STRIDE * 2) + kbyte + a_kb,
                       afh[mi]);
#pragma unroll
            for (int j = 0; j < 4; j++) {
                ldm_x4(bhb + (b_row + j * 16) * (GT_STRIDE * 2) + kbyte + b_kb,
                       bfh[j]);
                ldm_x4(blb + (b_row + j * 16) * (GT_STRIDE * 2) + kbyte + b_kb,
                       bfl[j]);
            }
#pragma unroll
            for (int mi = 0; mi < 2; mi++)
#pragma unroll
                for (int j = 0; j < 4; j++) {
                    mma_f16(acc[mi][2 * j],     afh[mi], bfh[j]);
                    mma_f16(acc[mi][2 * j + 1], afh[mi], bfh[j] + 2);
                    mma_f16(acc[mi][2 * j],     afh[mi], bfl[j]);
                    mma_f16(acc[mi][2 * j + 1], afh[mi], bfl[j] + 2);
                }
        }
        __syncthreads();
    }

    // ---- epilogue ----
    const int row_in = lane >> 2;
    const int col2 = 2 * (lane & 3);
#pragma unroll
    for (int mi = 0; mi < 2; mi++) {
#pragma unroll
        for (int h8 = 0; h8 < 2; h8++) {
            const size_t m = m0 + wm * 32 + mi * 16 + row_in + h8 * 8;
            float* dst;
            if (SCATTER == 0) {
                dst = C + m * NE + n0 + wn * 64;
            } else {
                const size_t hh = (n0 + wn * 64) / ND;
                const size_t bbi = m / NS, ss = m % NS;
                dst = C + ((bbi * NH + hh) * NS + ss) * ND;
            }
#pragma unroll
            for (int nj = 0; nj < 8; nj++) {
                float2 v = h8 ? make_float2(acc[mi][nj][2], acc[mi][nj][3])
                              : make_float2(acc[mi][nj][0], acc[mi][nj][1]);
                *reinterpret_cast<float2*>(dst + nj * 8 + col2) = v;
            }
        }
    }
}

// ======================= flash attention (fp32, 8x4 microtile) =============
// 128 threads: tx = tid&15 (4 k-cols each), ty = tid>>4 in 0..7 (8 q-rows each)
__global__ void __launch_bounds__(128)
attn_kernel(const float* __restrict__ Q, const float* __restrict__ K,
            const float* __restrict__ V, const int* __restrict__ amask,
            __half* __restrict__ Oh) {
    extern __shared__ float sm[];
    float* Qs = sm;
    float* Ks = sm + 64 * AST;
    float* Vs = sm + 2 * 64 * AST;
    float* Ps = sm + 3 * 64 * AST;

    const int tid = threadIdx.x;
    const int tx = tid & 15;
    const int ty = tid >> 4;
    const int qt = blockIdx.x;
    const int q0 = qt * 64;
    const int bh = blockIdx.y;
    const int b = bh / NH;
    const int h = bh % NH;

    const float* qbase = Q + (size_t)bh * NS * ND;
    const float* kbase = K + (size_t)bh * NS * ND;
    const float* vbase = V + (size_t)bh * NS * ND;

    for (int f = tid; f < 64 * 16; f += 128) {
        int r = f >> 4, cc = (f & 15) << 2;
        float4 v4 = *(const float4*)(qbase + (size_t)(q0 + r) * ND + cc);
        Qs[r * AST + cc + 0] = v4.x; Qs[r * AST + cc + 1] = v4.y;
        Qs[r * AST + cc + 2] = v4.z; Qs[r * AST + cc + 3] = v4.w;
    }

    float acco[8][4], rm[8], rl[8];
#pragma unroll
    for (int i = 0; i < 8; i++) {
        rm[i] = -1e30f; rl[i] = 0.f;
#pragma unroll
        for (int j = 0; j < 4; j++) acco[i][j] = 0.f;
    }
    const float scale = 0.125f;

    for (int kt = 0; kt <= qt; kt++) {
        const int k0 = kt * 64;
        __syncthreads();
        for (int f = tid; f < 64 * 16; f += 128) {
            int r = f >> 4, cc = (f & 15) << 2;
            float4 kv = *(const float4*)(kbase + (size_t)(k0 + r) * ND + cc);
            Ks[r * AST + cc + 0] = kv.x; Ks[r * AST + cc + 1] = kv.y;
            Ks[r * AST + cc + 2] = kv.z; Ks[r * AST + cc + 3] = kv.w;
            float4 vv = *(const float4*)(vbase + (size_t)(k0 + r) * ND + cc);
            Vs[r * AST + cc + 0] = vv.x; Vs[r * AST + cc + 1] = vv.y;
            Vs[r * AST + cc + 2] = vv.z; Vs[r * AST + cc + 3] = vv.w;
        }
        __syncthreads();

        float sacc[8][4];
#pragma unroll
        for (int i = 0; i < 8; i++)
#pragma unroll
            for (int j = 0; j < 4; j++) sacc[i][j] = 0.f;

#pragma unroll 8
        for (int d = 0; d < 64; d++) {
            float a[8], bq[4];
#pragma unroll
            for (int i = 0; i < 8; i++) a[i] = Qs[(8 * ty + i) * AST + d];
#pragma unroll
            for (int j = 0; j < 4; j++) bq[j] = Ks[(4 * tx + j) * AST + d];
#pragma unroll
            for (int i = 0; i < 8; i++)
#pragma unroll
                for (int j = 0; j < 4; j++)
                    sacc[i][j] = fmaf(a[i], bq[j], sacc[i][j]);
        }

        int pmv[4];
#pragma unroll
        for (int j = 0; j < 4; j++) pmv[j] = amask[b * NS + k0 + 4 * tx + j];
        const bool diag = (kt == qt);
#pragma unroll
        for (int i = 0; i < 8; i++) {
            int qi = q0 + 8 * ty + i;
#pragma unroll
            for (int j = 0; j < 4; j++) {
                int kj = k0 + 4 * tx + j;
                float s = sacc[i][j] * scale;
                if ((diag && kj > qi) || pmv[j] == 0) s = -1e30f;
                sacc[i][j] = s;
            }
        }

#pragma unroll
        for (int i = 0; i < 8; i++) {
            float mt = fmaxf(fmaxf(sacc[i][0], sacc[i][1]),
                             fmaxf(sacc[i][2], sacc[i][3]));
            mt = fmaxf(mt, __shfl_xor_sync(0xffffffffu, mt, 8));
            mt = fmaxf(mt, __shfl_xor_sync(0xffffffffu, mt, 4));
            mt = fmaxf(mt, __shfl_xor_sync(0xffffffffu, mt, 2));
            mt = fmaxf(mt, __shfl_xor_sync(0xffffffffu, mt, 1));
            float mnew = fmaxf(rm[i], mt);
            float fac = __expf(rm[i] - mnew);
            rm[i] = mnew;
            float psum = 0.f;
#pragma unroll
            for (int j = 0; j < 4; j++) {
                float p = __expf(sacc[i][j] - mnew);
                Ps[(8 * ty + i) * AST + 4 * tx + j] = p;
                psum += p;
            }
            psum += __shfl_xor_sync(0xffffffffu, psum, 8);
            psum += __shfl_xor_sync(0xffffffffu, psum, 4);
            psum += __shfl_xor_sync(0xffffffffu, psum, 2);
            psum += __shfl_xor_sync(0xffffffffu, psum, 1);
            rl[i] = rl[i] * fac + psum;
#pragma unroll
            for (int j = 0; j < 4; j++) acco[i][j] *= fac;
        }
        __syncthreads();

#pragma unroll 8
        for (int j = 0; j < 64; j++) {
            float a[8], vv[4];
#pragma unroll
            for (int i = 0; i < 8; i++) a[i] = Ps[(8 * ty + i) * AST + j];
#pragma unroll
            for (int jj = 0; jj < 4; jj++) vv[jj] = Vs[j * AST + 4 * tx + jj];
#pragma unroll
            for (int i = 0; i < 8; i++)
#pragma unroll
                for (int jj = 0; jj < 4; jj++)
                    acco[i][jj] = fmaf(a[i], vv[jj], acco[i][jj]);
        }
    }

    // epilogue: fp16 hi of [B,S,E]
#pragma unroll
    for (int i = 0; i < 8; i++) {
        float inv = 1.f / rl[i];
        size_t base = ((size_t)(b * NS + q0 + 8 * ty + i)) * NE + h * ND + 4 * tx;
        __half2 p0 = __floats2half2_rn(acco[i][0] * inv, acco[i][1] * inv);
        __half2 p1 = __floats2half2_rn(acco[i][2] * inv, acco[i][3] * inv);
        *reinterpret_cast<__half2*>(Oh + base)     = p0;
        *reinterpret_cast<__half2*>(Oh + base + 2) = p1;
    }
}

// ======================= launcher ==========================================
extern "C" void kernel_launch(void* const* d_in, const int* in_sizes, int n_in,
                              void* d_out, int out_size) {
    (void)in_sizes; (void)n_in; (void)out_size;
    const float* x  = (const float*)d_in[0];
    const int*   am = (const int*)d_in[1];
    const float* wq = (const float*)d_in[2];
    const float* wk = (const float*)d_in[3];
    const float* wv = (const float*)d_in[4];
    const float* wo = (const float*)d_in[5];
    float* out = (float*)d_out;

    float *q, *k, *v;
    __half *xh, *ah;
    __half *wqh, *wql, *wkh, *wkl, *wvh, *wvl, *woh, *wol;
    cudaGetSymbolAddress((void**)&q, g_q);
    cudaGetSymbolAddress((void**)&k, g_k);
    cudaGetSymbolAddress((void**)&v, g_v);
    cudaGetSymbolAddress((void**)&xh, g_xh);
    cudaGetSymbolAddress((void**)&ah, g_ah);
    cudaGetSymbolAddress((void**)&wqh, g_wqh);
    cudaGetSymbolAddress((void**)&wql, g_wql);
    cudaGetSymbolAddress((void**)&wkh, g_wkh);
    cudaGetSymbolAddress((void**)&wkl, g_wkl);
    cudaGetSymbolAddress((void**)&wvh, g_wvh);
    cudaGetSymbolAddress((void**)&wvl, g_wvl);
    cudaGetSymbolAddress((void**)&woh, g_woh);
    cudaGetSymbolAddress((void**)&wol, g_wol);

    const int NX4 = NB * NS * NE / 4, NW4 = NE * NE / 4;
    cvt_hi<<<(NX4 + 255) / 256, 256>>>(x, xh, NX4);
    cvt_split16<<<(NW4 + 255) / 256, 256>>>(wq, wqh, wql, NW4);
    cvt_split16<<<(NW4 + 255) / 256, 256>>>(wk, wkh, wkl, NW4);
    cvt_split16<<<(NW4 + 255) / 256, 256>>>(wv, wvh, wvl, NW4);
    cvt_split16<<<(NW4 + 255) / 256, 256>>>(wo, woh, wol, NW4);

    cudaFuncSetAttribute(gemm_mma<0>, cudaFuncAttributeMaxDynamicSharedMemorySize, GT_TOTAL);
    cudaFuncSetAttribute(gemm_mma<1>, cudaFuncAttributeMaxDynamicSharedMemorySize, GT_TOTAL);

    const dim3 gg(NE / 128, (NB * NS) / 128);  // (8, 64)
    gemm_mma<1><<<gg, 256, GT_TOTAL>>>(xh, wqh, wql, q);
    gemm_mma<1><<<gg, 256, GT_TOTAL>>>(xh, wkh, wkl, k);
    gemm_mma<1><<<gg, 256, GT_TOTAL>>>(xh, wvh, wvl, v);

    const int ATTN_SMEM = 4 * 64 * AST * (int)sizeof(float);
    cudaFuncSetAttribute(attn_kernel,
                         cudaFuncAttributeMaxDynamicSharedMemorySize, ATTN_SMEM);
    attn_kernel<<<dim3(NS / 64, NB * NH), 128, ATTN_SMEM>>>(q, k, v, am, ah);

    gemm_mma<0><<<gg, 256, GT_TOTAL>>>(ah, woh, wol, out);
}

// round 9
// speedup vs baseline: 1.9856x; 1.0483x over previous
#include <cuda_runtime.h>
#include <cuda_fp16.h>
#include <cstdint>

#define NB 4
#define NS 2048
#define NE 1024
#define NH 16
#define ND 64
#define AST 65

// ======================= scratch (allocation-free) =========================
__device__ float g_q[(size_t)NB * NH * NS * ND];
__device__ float g_k[(size_t)NB * NH * NS * ND];
__device__ float g_v[(size_t)NB * NH * NS * ND];
__device__ __half g_xh[(size_t)NB * NS * NE];
__device__ __half g_ah[(size_t)NB * NS * NE];
__device__ __half g_wqh[(size_t)NE * NE];
__device__ __half g_wql[(size_t)NE * NE];
__device__ __half g_wkh[(size_t)NE * NE];
__device__ __half g_wkl[(size_t)NE * NE];
__device__ __half g_wvh[(size_t)NE * NE];
__device__ __half g_wvl[(size_t)NE * NE];
__device__ __half g_woh[(size_t)NE * NE];
__device__ __half g_wol[(size_t)NE * NE];

// ======================= warp-level MMA helpers ============================
__device__ __forceinline__ uint32_t smem_u32(const void* p) {
    uint32_t a;
    asm("{ .reg .u64 t; cvta.to.shared.u64 t, %1; cvt.u32.u64 %0, t; }"
        : "=r"(a) : "l"(p));
    return a;
}
__device__ __forceinline__ void ldm_x4(uint32_t addr, uint32_t* r) {
    asm volatile("ldmatrix.sync.aligned.m8n8.x4.shared.b16 {%0,%1,%2,%3}, [%4];"
                 : "=r"(r[0]), "=r"(r[1]), "=r"(r[2]), "=r"(r[3]) : "r"(addr));
}
__device__ __forceinline__ void mma_f16(float* d, const uint32_t* a,
                                        const uint32_t* b) {
    asm volatile(
        "mma.sync.aligned.m16n8k16.row.col.f32.f16.f16.f32 "
        "{%0,%1,%2,%3}, {%4,%5,%6,%7}, {%8,%9}, {%0,%1,%2,%3};"
        : "+f"(d[0]), "+f"(d[1]), "+f"(d[2]), "+f"(d[3])
        : "r"(a[0]), "r"(a[1]), "r"(a[2]), "r"(a[3]), "r"(b[0]), "r"(b[1]));
}
#define CP_ASYNC16(dst, src)                                                   \
    asm volatile("cp.async.ca.shared.global [%0], [%1], 16;"                   \
                 :: "r"(dst), "l"(src) : "memory")
#define CP_COMMIT() asm volatile("cp.async.commit_group;" ::: "memory")
#define CP_WAIT1()  asm volatile("cp.async.wait_group 1;" ::: "memory")
#define CP_WAIT0()  asm volatile("cp.async.wait_group 0;" ::: "memory")

// ======================= conversion kernels ================================
__global__ void __launch_bounds__(256)
cvt_hi(const float* __restrict__ src, __half* __restrict__ hi, int n4) {
    int i = blockIdx.x * 256 + threadIdx.x;
    if (i >= n4) return;
    float4 v = reinterpret_cast<const float4*>(src)[i];
    __half2 p0 = __floats2half2_rn(v.x, v.y);
    __half2 p1 = __floats2half2_rn(v.z, v.w);
    reinterpret_cast<__half2*>(hi)[2 * i]     = p0;
    reinterpret_cast<__half2*>(hi)[2 * i + 1] = p1;
}

__global__ void __launch_bounds__(256)
cvt_split16(const float* __restrict__ src, __half* __restrict__ hi,
            __half* __restrict__ lo, int n4) {
    int i = blockIdx.x * 256 + threadIdx.x;
    if (i >= n4) return;
    float4 v = reinterpret_cast<const float4*>(src)[i];
    __half h0 = __float2half_rn(v.x);
    __half h1 = __float2half_rn(v.y);
    __half h2 = __float2half_rn(v.z);
    __half h3 = __float2half_rn(v.w);
    __half l0 = __float2half_rn(v.x - __half2float(h0));
    __half l1 = __float2half_rn(v.y - __half2float(h1));
    __half l2 = __float2half_rn(v.z - __half2float(h2));
    __half l3 = __float2half_rn(v.w - __half2float(h3));
    reinterpret_cast<__half2*>(hi)[2 * i]     = __halves2half2(h0, h1);
    reinterpret_cast<__half2*>(hi)[2 * i + 1] = __halves2half2(h2, h3);
    reinterpret_cast<__half2*>(lo)[2 * i]     = __halves2half2(l0, l1);
    reinterpret_cast<__half2*>(lo)[2 * i + 1] = __halves2half2(l2, l3);
}

// ======================= fp16 2-pass GEMM via mma.sync =====================
// C[M,N] = A @ W^T;  D = Ah*Wh + Ah*Wl  (fp32 accum).
// CTA 128x128, 4 warps (2m x 2n), warp tile 64x64 (high MMA:LDSM ratio).
// K-chunk 32, 3-stage cp.async pipeline, 3 smem tiles per stage.
#define GT_STRIDE 40                        // halves per smem row (80 B)
#define GT_TILE_B (128 * GT_STRIDE * 2)     // 10240 B per tile
#define GT_STAGE_B (3 * GT_TILE_B)          // Ah, Wh, Wl = 30720 B
#define GT_TOTAL (3 * GT_STAGE_B)           // 92160 B

template <int SCATTER>
__global__ void __launch_bounds__(128, 2)
gemm_mma(const __half* __restrict__ Ah, const __half* __restrict__ Bh,
         const __half* __restrict__ Bl, float* __restrict__ C) {
    extern __shared__ __align__(128) char smem[];
    const uint32_t sb = smem_u32(smem);
    const int tid = threadIdx.x;
    const int wid = tid >> 5, lane = tid & 31;
    const int wm = wid & 1, wn = wid >> 1;
    const size_t m0 = (size_t)blockIdx.y * 128;
    const size_t n0 = (size_t)blockIdx.x * 128;

    const __half* srcs[3] = {Ah, Bh, Bl};

    auto issue_chunk = [&](int c, int buf) {
        const int kofs = c * 32;
        const uint32_t base = sb + buf * GT_STAGE_B;
#pragma unroll
        for (int it = 0; it < 12; it++) {
            const int t = it >> 2;                 // tile: 0=A, 1=Bh, 2=Bl
            const int s = tid + (it & 3) * 128;    // 0..511
            const int r = s >> 2;                  // 0..127
            const int g = s & 3;
            const size_t row = (t == 0 ? m0 : n0) + r;
            const __half* gsrc = srcs[t] + row * NE + kofs + g * 8;
            const uint32_t dst = base + t * GT_TILE_B + r * (GT_STRIDE * 2) + g * 16;
            CP_ASYNC16(dst, gsrc);
        }
        CP_COMMIT();
    };

    float acc[4][8][4];
#pragma unroll
    for (int mi = 0; mi < 4; mi++)
#pragma unroll
        for (int nj = 0; nj < 8; nj++)
#pragma unroll
            for (int e = 0; e < 4; e++) acc[mi][nj][e] = 0.f;

    const int a_row = wm * 64 + (lane & 15);
    const int a_kb  = (lane >> 4) * 16;
    const int b_row = wn * 64 + (lane >> 4) * 8 + (lane & 7);
    const int b_kb  = ((lane >> 3) & 1) * 16;

    issue_chunk(0, 0);
    issue_chunk(1, 1);
    for (int c = 0; c < 32; c++) {
        const int buf = c % 3;
        if (c < 31) CP_WAIT1(); else CP_WAIT0();
        __syncthreads();
        if (c + 2 < 32) issue_chunk(c + 2, (c + 2) % 3);

        const uint32_t ahb = sb + buf * GT_STAGE_B;
        const uint32_t bhb = ahb + GT_TILE_B;
        const uint32_t blb = ahb + 2 * GT_TILE_B;

#pragma unroll
        for (int kk = 0; kk < 2; kk++) {
            const int kbyte = kk * 32;
            uint32_t afh[4][4], bfh[4][4], bfl[4][4];
#pragma unroll
            for (int mi = 0; mi < 4; mi++)
                ldm_x4(ahb + (a_row + mi * 16) * (GT_STRIDE * 2) + kbyte + a_kb,
                       afh[mi]);
#pragma unroll
            for (int j = 0; j < 4; j++) {
                ldm_x4(bhb + (b_row + j * 16) * (GT_STRIDE * 2) + kbyte + b_kb,
                       bfh[j]);
                ldm_x4(blb + (b_row + j * 16) * (GT_STRIDE * 2) + kbyte + b_kb,
                       bfl[j]);
            }
#pragma unroll
            for (int mi = 0; mi < 4; mi++)
#pragma unroll
                for (int j = 0; j < 4; j++) {
                    mma_f16(acc[mi][2 * j],     afh[mi], bfh[j]);
                    mma_f16(acc[mi][2 * j + 1], afh[mi], bfh[j] + 2);
                    mma_f16(acc[mi][2 * j],     afh[mi], bfl[j]);
                    mma_f16(acc[mi][2 * j + 1], afh[mi], bfl[j] + 2);
                }
        }
        __syncthreads();
    }

    // ---- epilogue ----
    const int row_in = lane >> 2;
    const int col2 = 2 * (lane & 3);
#pragma unroll
    for (int mi = 0; mi < 4; mi++) {
#pragma unroll
        for (int h8 = 0; h8 < 2; h8++) {
            const size_t m = m0 + wm * 64 + mi * 16 + row_in + h8 * 8;
            float* dst;
            if (SCATTER == 0) {
                dst = C + m * NE + n0 + wn * 64;
            } else {
                const size_t hh = (n0 + wn * 64) / ND;
                const size_t bbi = m / NS, ss = m % NS;
                dst = C + ((bbi * NH + hh) * NS + ss) * ND;
            }
#pragma unroll
            for (int nj = 0; nj < 8; nj++) {
                float2 v = h8 ? make_float2(acc[mi][nj][2], acc[mi][nj][3])
                              : make_float2(acc[mi][nj][0], acc[mi][nj][1]);
                *reinterpret_cast<float2*>(dst + nj * 8 + col2) = v;
            }
        }
    }
}

// ======================= flash attention (fp32, 8x4 microtile) =============
// 128 threads: tx = tid&15 (4 k-cols each), ty = tid>>4 in 0..7 (8 q-rows each)
__global__ void __launch_bounds__(128)
attn_kernel(const float* __restrict__ Q, const float* __restrict__ K,
            const float* __restrict__ V, const int* __restrict__ amask,
            __half* __restrict__ Oh) {
    extern __shared__ float sm[];
    float* Qs = sm;
    float* Ks = sm + 64 * AST;
    float* Vs = sm + 2 * 64 * AST;
    float* Ps = sm + 3 * 64 * AST;

    const int tid = threadIdx.x;
    const int tx = tid & 15;
    const int ty = tid >> 4;
    const int qt = blockIdx.x;
    const int q0 = qt * 64;
    const int bh = blockIdx.y;
    const int b = bh / NH;
    const int h = bh % NH;

    const float* qbase = Q + (size_t)bh * NS * ND;
    const float* kbase = K + (size_t)bh * NS * ND;
    const float* vbase = V + (size_t)bh * NS * ND;

    for (int f = tid; f < 64 * 16; f += 128) {
        int r = f >> 4, cc = (f & 15) << 2;
        float4 v4 = *(const float4*)(qbase + (size_t)(q0 + r) * ND + cc);
        Qs[r * AST + cc + 0] = v4.x; Qs[r * AST + cc + 1] = v4.y;
        Qs[r * AST + cc + 2] = v4.z; Qs[r * AST + cc + 3] = v4.w;
    }

    float acco[8][4], rm[8], rl[8];
#pragma unroll
    for (int i = 0; i < 8; i++) {
        rm[i] = -1e30f; rl[i] = 0.f;
#pragma unroll
        for (int j = 0; j < 4; j++) acco[i][j] = 0.f;
    }
    const float scale = 0.125f;

    for (int kt = 0; kt <= qt; kt++) {
        const int k0 = kt * 64;
        __syncthreads();
        for (int f = tid; f < 64 * 16; f += 128) {
            int r = f >> 4, cc = (f & 15) << 2;
            float4 kv = *(const float4*)(kbase + (size_t)(k0 + r) * ND + cc);
            Ks[r * AST + cc + 0] = kv.x; Ks[r * AST + cc + 1] = kv.y;
            Ks[r * AST + cc + 2] = kv.z; Ks[r * AST + cc + 3] = kv.w;
            float4 vv = *(const float4*)(vbase + (size_t)(k0 + r) * ND + cc);
            Vs[r * AST + cc + 0] = vv.x; Vs[r * AST + cc + 1] = vv.y;
            Vs[r * AST + cc + 2] = vv.z; Vs[r * AST + cc + 3] = vv.w;
        }
        __syncthreads();

        float sacc[8][4];
#pragma unroll
        for (int i = 0; i < 8; i++)
#pragma unroll
            for (int j = 0; j < 4; j++) sacc[i][j] = 0.f;

#pragma unroll 8
        for (int d = 0; d < 64; d++) {
            float a[8], bq[4];
#pragma unroll
            for (int i = 0; i < 8; i++) a[i] = Qs[(8 * ty + i) * AST + d];
#pragma unroll
            for (int j = 0; j < 4; j++) bq[j] = Ks[(4 * tx + j) * AST + d];
#pragma unroll
            for (int i = 0; i < 8; i++)
#pragma unroll
                for (int j = 0; j < 4; j++)
                    sacc[i][j] = fmaf(a[i], bq[j], sacc[i][j]);
        }

        int pmv[4];
#pragma unroll
        for (int j = 0; j < 4; j++) pmv[j] = amask[b * NS + k0 + 4 * tx + j];
        const bool diag = (kt == qt);
#pragma unroll
        for (int i = 0; i < 8; i++) {
            int qi = q0 + 8 * ty + i;
#pragma unroll
            for (int j = 0; j < 4; j++) {
                int kj = k0 + 4 * tx + j;
                float s = sacc[i][j] * scale;
                if ((diag && kj > qi) || pmv[j] == 0) s = -1e30f;
                sacc[i][j] = s;
            }
        }

#pragma unroll
        for (int i = 0; i < 8; i++) {
            float mt = fmaxf(fmaxf(sacc[i][0], sacc[i][1]),
                             fmaxf(sacc[i][2], sacc[i][3]));
            mt = fmaxf(mt, __shfl_xor_sync(0xffffffffu, mt, 8));
            mt = fmaxf(mt, __shfl_xor_sync(0xffffffffu, mt, 4));
            mt = fmaxf(mt, __shfl_xor_sync(0xffffffffu, mt, 2));
            mt = fmaxf(mt, __shfl_xor_sync(0xffffffffu, mt, 1));
            float mnew = fmaxf(rm[i], mt);
            float fac = __expf(rm[i] - mnew);
            rm[i] = mnew;
            float psum = 0.f;
#pragma unroll
            for (int j = 0; j < 4; j++) {
                float p = __expf(sacc[i][j] - mnew);
                Ps[(8 * ty + i) * AST + 4 * tx + j] = p;
                psum += p;
            }
            psum += __shfl_xor_sync(0xffffffffu, psum, 8);
            psum += __shfl_xor_sync(0xffffffffu, psum, 4);
            psum += __shfl_xor_sync(0xffffffffu, psum, 2);
            psum += __shfl_xor_sync(0xffffffffu, psum, 1);
            rl[i] = rl[i] * fac + psum;
#pragma unroll
            for (int j = 0; j < 4; j++) acco[i][j] *= fac;
        }
        __syncthreads();

#pragma unroll 8
        for (int j = 0; j < 64; j++) {
            float a[8], vv[4];
#pragma unroll
            for (int i = 0; i < 8; i++) a[i] = Ps[(8 * ty + i) * AST + j];
#pragma unroll
            for (int jj = 0; jj < 4; jj++) vv[jj] = Vs[j * AST + 4 * tx + jj];
#pragma unroll
            for (int i = 0; i < 8; i++)
#pragma unroll
                for (int jj = 0; jj < 4; jj++)
                    acco[i][jj] = fmaf(a[i], vv[jj], acco[i][jj]);
        }
    }

    // epilogue: fp16 hi of [B,S,E]
#pragma unroll
    for (int i = 0; i < 8; i++) {
        float inv = 1.f / rl[i];
        size_t base = ((size_t)(b * NS + q0 + 8 * ty + i)) * NE + h * ND + 4 * tx;
        __half2 p0 = __floats2half2_rn(acco[i][0] * inv, acco[i][1] * inv);
        __half2 p1 = __floats2half2_rn(acco[i][2] * inv, acco[i][3] * inv);
        *reinterpret_cast<__half2*>(Oh + base)     = p0;
        *reinterpret_cast<__half2*>(Oh + base + 2) = p1;
    }
}

// ======================= launcher ==========================================
extern "C" void kernel_launch(void* const* d_in, const int* in_sizes, int n_in,
                              void* d_out, int out_size) {
    (void)in_sizes; (void)n_in; (void)out_size;
    const float* x  = (const float*)d_in[0];
    const int*   am = (const int*)d_in[1];
    const float* wq = (const float*)d_in[2];
    const float* wk = (const float*)d_in[3];
    const float* wv = (const float*)d_in[4];
    const float* wo = (const float*)d_in[5];
    float* out = (float*)d_out;

    float *q, *k, *v;
    __half *xh, *ah;
    __half *wqh, *wql, *wkh, *wkl, *wvh, *wvl, *woh, *wol;
    cudaGetSymbolAddress((void**)&q, g_q);
    cudaGetSymbolAddress((void**)&k, g_k);
    cudaGetSymbolAddress((void**)&v, g_v);
    cudaGetSymbolAddress((void**)&xh, g_xh);
    cudaGetSymbolAddress((void**)&ah, g_ah);
    cudaGetSymbolAddress((void**)&wqh, g_wqh);
    cudaGetSymbolAddress((void**)&wql, g_wql);
    cudaGetSymbolAddress((void**)&wkh, g_wkh);
    cudaGetSymbolAddress((void**)&wkl, g_wkl);
    cudaGetSymbolAddress((void**)&wvh, g_wvh);
    cudaGetSymbolAddress((void**)&wvl, g_wvl);
    cudaGetSymbolAddress((void**)&woh, g_woh);
    cudaGetSymbolAddress((void**)&wol, g_wol);

    const int NX4 = NB * NS * NE / 4, NW4 = NE * NE / 4;
    cvt_hi<<<(NX4 + 255) / 256, 256>>>(x, xh, NX4);
    cvt_split16<<<(NW4 + 255) / 256, 256>>>(wq, wqh, wql, NW4);
    cvt_split16<<<(NW4 + 255) / 256, 256>>>(wk, wkh, wkl, NW4);
    cvt_split16<<<(NW4 + 255) / 256, 256>>>(wv, wvh, wvl, NW4);
    cvt_split16<<<(NW4 + 255) / 256, 256>>>(wo, woh, wol, NW4);

    cudaFuncSetAttribute(gemm_mma<0>, cudaFuncAttributeMaxDynamicSharedMemorySize, GT_TOTAL);
    cudaFuncSetAttribute(gemm_mma<1>, cudaFuncAttributeMaxDynamicSharedMemorySize, GT_TOTAL);

    const dim3 gg(NE / 128, (NB * NS) / 128);  // (8, 64)
    gemm_mma<1><<<gg, 128, GT_TOTAL>>>(xh, wqh, wql, q);
    gemm_mma<1><<<gg, 128, GT_TOTAL>>>(xh, wkh, wkl, k);
    gemm_mma<1><<<gg, 128, GT_TOTAL>>>(xh, wvh, wvl, v);

    const int ATTN_SMEM = 4 * 64 * AST * (int)sizeof(float);
    cudaFuncSetAttribute(attn_kernel,
                         cudaFuncAttributeMaxDynamicSharedMemorySize, ATTN_SMEM);
    attn_kernel<<<dim3(NS / 64, NB * NH), 128, ATTN_SMEM>>>(q, k, v, am, ah);

    gemm_mma<0><<<gg, 128, GT_TOTAL>>>(ah, woh, wol, out);
}

// round 10
// speedup vs baseline: 2.3362x; 1.1765x over previous
#include <cuda_runtime.h>
#include <cuda_fp16.h>
#include <cstdint>

#define NB 4
#define NS 2048
#define NE 1024
#define NH 16
#define ND 64
#define AST 65

// ======================= scratch (allocation-free) =========================
__device__ float g_q[(size_t)NB * NH * NS * ND];
__device__ float g_k[(size_t)NB * NH * NS * ND];
__device__ float g_v[(size_t)NB * NH * NS * ND];
__device__ __half g_xh[(size_t)NB * NS * NE];
__device__ __half g_ah[(size_t)NB * NS * NE];
__device__ __half g_wqkv[(size_t)3 * NE * NE];  // wq | wk | wv rows
__device__ __half g_woh[(size_t)NE * NE];

// ======================= warp-level MMA helpers ============================
__device__ __forceinline__ uint32_t smem_u32(const void* p) {
    uint32_t a;
    asm("{ .reg .u64 t; cvta.to.shared.u64 t, %1; cvt.u32.u64 %0, t; }"
        : "=r"(a) : "l"(p));
    return a;
}
__device__ __forceinline__ void ldm_x4(uint32_t addr, uint32_t* r) {
    asm volatile("ldmatrix.sync.aligned.m8n8.x4.shared.b16 {%0,%1,%2,%3}, [%4];"
                 : "=r"(r[0]), "=r"(r[1]), "=r"(r[2]), "=r"(r[3]) : "r"(addr));
}
__device__ __forceinline__ void mma_f16(float* d, const uint32_t* a,
                                        const uint32_t* b) {
    asm volatile(
        "mma.sync.aligned.m16n8k16.row.col.f32.f16.f16.f32 "
        "{%0,%1,%2,%3}, {%4,%5,%6,%7}, {%8,%9}, {%0,%1,%2,%3};"
        : "+f"(d[0]), "+f"(d[1]), "+f"(d[2]), "+f"(d[3])
        : "r"(a[0]), "r"(a[1]), "r"(a[2]), "r"(a[3]), "r"(b[0]), "r"(b[1]));
}
#define CP_ASYNC16(dst, src)                                                   \
    asm volatile("cp.async.ca.shared.global [%0], [%1], 16;"                   \
                 :: "r"(dst), "l"(src) : "memory")
#define CP_COMMIT() asm volatile("cp.async.commit_group;" ::: "memory")
#define CP_WAIT1()  asm volatile("cp.async.wait_group 1;" ::: "memory")
#define CP_WAIT0()  asm volatile("cp.async.wait_group 0;" ::: "memory")

// ======================= conversion kernel =================================
__global__ void __launch_bounds__(256)
cvt_hi(const float* __restrict__ src, __half* __restrict__ hi, int n4) {
    int i = blockIdx.x * 256 + threadIdx.x;
    if (i >= n4) return;
    float4 v = reinterpret_cast<const float4*>(src)[i];
    __half2 p0 = __floats2half2_rn(v.x, v.y);
    __half2 p1 = __floats2half2_rn(v.z, v.w);
    reinterpret_cast<__half2*>(hi)[2 * i]     = p0;
    reinterpret_cast<__half2*>(hi)[2 * i + 1] = p1;
}

// ======================= fp16 1-pass GEMM via mma.sync =====================
// C = A @ W^T (fp32 accum). CTA 128x128, 4 warps (2m x 2n), warp tile 64x64.
// K-chunk 32, 3-stage cp.async pipeline, 2 smem tiles (A, B) per stage.
// SCATTER=1: fused QKV — B rows span [3*NE, NE]; n selects q/k/v + head.
#define GT_STRIDE 40                        // halves per smem row (80 B)
#define GT_TILE_B (128 * GT_STRIDE * 2)     // 10240 B per tile
#define GT_STAGE_B (2 * GT_TILE_B)          // A, B = 20480 B
#define GT_TOTAL (3 * GT_STAGE_B)           // 61440 B

template <int SCATTER>
__global__ void __launch_bounds__(128, 2)
gemm_mma(const __half* __restrict__ Ah, const __half* __restrict__ Bh,
         float* __restrict__ C0, float* __restrict__ C1,
         float* __restrict__ C2) {
    extern __shared__ __align__(128) char smem[];
    const uint32_t sb = smem_u32(smem);
    const int tid = threadIdx.x;
    const int wid = tid >> 5, lane = tid & 31;
    const int wm = wid & 1, wn = wid >> 1;
    const size_t m0 = (size_t)blockIdx.y * 128;
    const size_t n0 = (size_t)blockIdx.x * 128;

    auto issue_chunk = [&](int c, int buf) {
        const int kofs = c * 32;
        const uint32_t base = sb + buf * GT_STAGE_B;
#pragma unroll
        for (int it = 0; it < 8; it++) {
            const int t = it >> 2;                 // 0=A, 1=B
            const int s = tid + (it & 3) * 128;    // 0..511
            const int r = s >> 2;                  // 0..127
            const int g = s & 3;
            const size_t row = (t == 0 ? m0 : n0) + r;
            const __half* gsrc = (t == 0 ? Ah : Bh) + row * NE + kofs + g * 8;
            const uint32_t dst = base + t * GT_TILE_B + r * (GT_STRIDE * 2) + g * 16;
            CP_ASYNC16(dst, gsrc);
        }
        CP_COMMIT();
    };

    float acc[4][8][4];
#pragma unroll
    for (int mi = 0; mi < 4; mi++)
#pragma unroll
        for (int nj = 0; nj < 8; nj++)
#pragma unroll
            for (int e = 0; e < 4; e++) acc[mi][nj][e] = 0.f;

    const int a_row = wm * 64 + (lane & 15);
    const int a_kb  = (lane >> 4) * 16;
    const int b_row = wn * 64 + (lane >> 4) * 8 + (lane & 7);
    const int b_kb  = ((lane >> 3) & 1) * 16;

    issue_chunk(0, 0);
    issue_chunk(1, 1);
    for (int c = 0; c < 32; c++) {
        const int buf = c % 3;
        if (c < 31) CP_WAIT1(); else CP_WAIT0();
        __syncthreads();
        if (c + 2 < 32) issue_chunk(c + 2, (c + 2) % 3);

        const uint32_t ahb = sb + buf * GT_STAGE_B;
        const uint32_t bhb = ahb + GT_TILE_B;

#pragma unroll
        for (int kk = 0; kk < 2; kk++) {
            const int kbyte = kk * 32;
            uint32_t afh[4][4], bfh[4][4];
#pragma unroll
            for (int mi = 0; mi < 4; mi++)
                ldm_x4(ahb + (a_row + mi * 16) * (GT_STRIDE * 2) + kbyte + a_kb,
                       afh[mi]);
#pragma unroll
            for (int j = 0; j < 4; j++)
                ldm_x4(bhb + (b_row + j * 16) * (GT_STRIDE * 2) + kbyte + b_kb,
                       bfh[j]);
#pragma unroll
            for (int mi = 0; mi < 4; mi++)
#pragma unroll
                for (int j = 0; j < 4; j++) {
                    mma_f16(acc[mi][2 * j],     afh[mi], bfh[j]);
                    mma_f16(acc[mi][2 * j + 1], afh[mi], bfh[j] + 2);
                }
        }
        __syncthreads();
    }

    // ---- epilogue ----
    const int row_in = lane >> 2;
    const int col2 = 2 * (lane & 3);
    // scatter target resolution (whole 64-col warp half is one projection+head)
    float* cbase = C0;
    size_t hh = 0;
    if (SCATTER) {
        const size_t nglob = n0 + wn * 64;
        const int tsel = (int)(nglob >> 10);
        cbase = tsel == 0 ? C0 : (tsel == 1 ? C1 : C2);
        hh = (nglob & 1023) >> 6;
    }
#pragma unroll
    for (int mi = 0; mi < 4; mi++) {
#pragma unroll
        for (int h8 = 0; h8 < 2; h8++) {
            const size_t m = m0 + wm * 64 + mi * 16 + row_in + h8 * 8;
            float* dst;
            if (SCATTER == 0) {
                dst = C0 + m * NE + n0 + wn * 64;
            } else {
                const size_t bbi = m / NS, ss = m % NS;
                dst = cbase + ((bbi * NH + hh) * NS + ss) * ND;
            }
#pragma unroll
            for (int nj = 0; nj < 8; nj++) {
                float2 v = h8 ? make_float2(acc[mi][nj][2], acc[mi][nj][3])
                              : make_float2(acc[mi][nj][0], acc[mi][nj][1]);
                *reinterpret_cast<float2*>(dst + nj * 8 + col2) = v;
            }
        }
    }
}

// ======================= flash attention (fp32, 8x4 microtile) =============
__global__ void __launch_bounds__(128)
attn_kernel(const float* __restrict__ Q, const float* __restrict__ K,
            const float* __restrict__ V, const int* __restrict__ amask,
            __half* __restrict__ Oh) {
    extern __shared__ float sm[];
    float* Qs = sm;
    float* Ks = sm + 64 * AST;
    float* Vs = sm + 2 * 64 * AST;
    float* Ps = sm + 3 * 64 * AST;

    const int tid = threadIdx.x;
    const int tx = tid & 15;
    const int ty = tid >> 4;
    const int qt = blockIdx.x;
    const int q0 = qt * 64;
    const int bh = blockIdx.y;
    const int b = bh / NH;
    const int h = bh % NH;

    const float* qbase = Q + (size_t)bh * NS * ND;
    const float* kbase = K + (size_t)bh * NS * ND;
    const float* vbase = V + (size_t)bh * NS * ND;

    for (int f = tid; f < 64 * 16; f += 128) {
        int r = f >> 4, cc = (f & 15) << 2;
        float4 v4 = *(const float4*)(qbase + (size_t)(q0 + r) * ND + cc);
        Qs[r * AST + cc + 0] = v4.x; Qs[r * AST + cc + 1] = v4.y;
        Qs[r * AST + cc + 2] = v4.z; Qs[r * AST + cc + 3] = v4.w;
    }

    float acco[8][4], rm[8], rl[8];
#pragma unroll
    for (int i = 0; i < 8; i++) {
        rm[i] = -1e30f; rl[i] = 0.f;
#pragma unroll
        for (int j = 0; j < 4; j++) acco[i][j] = 0.f;
    }
    const float scale = 0.125f;

    for (int kt = 0; kt <= qt; kt++) {
        const int k0 = kt * 64;
        __syncthreads();
        for (int f = tid; f < 64 * 16; f += 128) {
            int r = f >> 4, cc = (f & 15) << 2;
            float4 kv = *(const float4*)(kbase + (size_t)(k0 + r) * ND + cc);
            Ks[r * AST + cc + 0] = kv.x; Ks[r * AST + cc + 1] = kv.y;
            Ks[r * AST + cc + 2] = kv.z; Ks[r * AST + cc + 3] = kv.w;
            float4 vv = *(const float4*)(vbase + (size_t)(k0 + r) * ND + cc);
            Vs[r * AST + cc + 0] = vv.x; Vs[r * AST + cc + 1] = vv.y;
            Vs[r * AST + cc + 2] = vv.z; Vs[r * AST + cc + 3] = vv.w;
        }
        __syncthreads();

        float sacc[8][4];
#pragma unroll
        for (int i = 0; i < 8; i++)
#pragma unroll
            for (int j = 0; j < 4; j++) sacc[i][j] = 0.f;

#pragma unroll 8
        for (int d = 0; d < 64; d++) {
            float a[8], bq[4];
#pragma unroll
            for (int i = 0; i < 8; i++) a[i] = Qs[(8 * ty + i) * AST + d];
#pragma unroll
            for (int j = 0; j < 4; j++) bq[j] = Ks[(4 * tx + j) * AST + d];
#pragma unroll
            for (int i = 0; i < 8; i++)
#pragma unroll
                for (int j = 0; j < 4; j++)
                    sacc[i][j] = fmaf(a[i], bq[j], sacc[i][j]);
        }

        int pmv[4];
#pragma unroll
        for (int j = 0; j < 4; j++) pmv[j] = amask[b * NS + k0 + 4 * tx + j];
        const bool diag = (kt == qt);
#pragma unroll
        for (int i = 0; i < 8; i++) {
            int qi = q0 + 8 * ty + i;
#pragma unroll
            for (int j = 0; j < 4; j++) {
                int kj = k0 + 4 * tx + j;
                float s = sacc[i][j] * scale;
                if ((diag && kj > qi) || pmv[j] == 0) s = -1e30f;
                sacc[i][j] = s;
            }
        }

#pragma unroll
        for (int i = 0; i < 8; i++) {
            float mt = fmaxf(fmaxf(sacc[i][0], sacc[i][1]),
                             fmaxf(sacc[i][2], sacc[i][3]));
            mt = fmaxf(mt, __shfl_xor_sync(0xffffffffu, mt, 8));
            mt = fmaxf(mt, __shfl_xor_sync(0xffffffffu, mt, 4));
            mt = fmaxf(mt, __shfl_xor_sync(0xffffffffu, mt, 2));
            mt = fmaxf(mt, __shfl_xor_sync(0xffffffffu, mt, 1));
            float mnew = fmaxf(rm[i], mt);
            float fac = __expf(rm[i] - mnew);
            rm[i] = mnew;
            float psum = 0.f;
#pragma unroll
            for (int j = 0; j < 4; j++) {
                float p = __expf(sacc[i][j] - mnew);
                Ps[(8 * ty + i) * AST + 4 * tx + j] = p;
                psum += p;
            }
            psum += __shfl_xor_sync(0xffffffffu, psum, 8);
            psum += __shfl_xor_sync(0xffffffffu, psum, 4);
            psum += __shfl_xor_sync(0xffffffffu, psum, 2);
            psum += __shfl_xor_sync(0xffffffffu, psum, 1);
            rl[i] = rl[i] * fac + psum;
#pragma unroll
            for (int j = 0; j < 4; j++) acco[i][j] *= fac;
        }
        __syncthreads();

#pragma unroll 8
        for (int j = 0; j < 64; j++) {
            float a[8], vv[4];
#pragma unroll
            for (int i = 0; i < 8; i++) a[i] = Ps[(8 * ty + i) * AST + j];
#pragma unroll
            for (int jj = 0; jj < 4; jj++) vv[jj] = Vs[j * AST + 4 * tx + jj];
#pragma unroll
            for (int i = 0; i < 8; i++)
#pragma unroll
                for (int jj = 0; jj < 4; jj++)
                    acco[i][jj] = fmaf(a[i], vv[jj], acco[i][jj]);
        }
    }

#pragma unroll
    for (int i = 0; i < 8; i++) {
        float inv = 1.f / rl[i];
        size_t base = ((size_t)(b * NS + q0 + 8 * ty + i)) * NE + h * ND + 4 * tx;
        __half2 p0 = __floats2half2_rn(acco[i][0] * inv, acco[i][1] * inv);
        __half2 p1 = __floats2half2_rn(acco[i][2] * inv, acco[i][3] * inv);
        *reinterpret_cast<__half2*>(Oh + base)     = p0;
        *reinterpret_cast<__half2*>(Oh + base + 2) = p1;
    }
}

// ======================= launcher ==========================================
extern "C" void kernel_launch(void* const* d_in, const int* in_sizes, int n_in,
                              void* d_out, int out_size) {
    (void)in_sizes; (void)n_in; (void)out_size;
    const float* x  = (const float*)d_in[0];
    const int*   am = (const int*)d_in[1];
    const float* wq = (const float*)d_in[2];
    const float* wk = (const float*)d_in[3];
    const float* wv = (const float*)d_in[4];
    const float* wo = (const float*)d_in[5];
    float* out = (float*)d_out;

    float *q, *k, *v;
    __half *xh, *ah, *wqkv, *woh;
    cudaGetSymbolAddress((void**)&q, g_q);
    cudaGetSymbolAddress((void**)&k, g_k);
    cudaGetSymbolAddress((void**)&v, g_v);
    cudaGetSymbolAddress((void**)&xh, g_xh);
    cudaGetSymbolAddress((void**)&ah, g_ah);
    cudaGetSymbolAddress((void**)&wqkv, g_wqkv);
    cudaGetSymbolAddress((void**)&woh, g_woh);

    const int NX4 = NB * NS * NE / 4, NW4 = NE * NE / 4;
    cvt_hi<<<(NX4 + 255) / 256, 256>>>(x, xh, NX4);
    cvt_hi<<<(NW4 + 255) / 256, 256>>>(wq, wqkv, NW4);
    cvt_hi<<<(NW4 + 255) / 256, 256>>>(wk, wqkv + (size_t)NE * NE, NW4);
    cvt_hi<<<(NW4 + 255) / 256, 256>>>(wv, wqkv + (size_t)2 * NE * NE, NW4);
    cvt_hi<<<(NW4 + 255) / 256, 256>>>(wo, woh, NW4);

    cudaFuncSetAttribute(gemm_mma<0>, cudaFuncAttributeMaxDynamicSharedMemorySize, GT_TOTAL);
    cudaFuncSetAttribute(gemm_mma<1>, cudaFuncAttributeMaxDynamicSharedMemorySize, GT_TOTAL);

    // fused QKV: weight rows span 3*NE
    gemm_mma<1><<<dim3(3 * NE / 128, (NB * NS) / 128), 128, GT_TOTAL>>>(
        xh, wqkv, q, k, v);

    const int ATTN_SMEM = 4 * 64 * AST * (int)sizeof(float);
    cudaFuncSetAttribute(attn_kernel,
                         cudaFuncAttributeMaxDynamicSharedMemorySize, ATTN_SMEM);
    attn_kernel<<<dim3(NS / 64, NB * NH), 128, ATTN_SMEM>>>(q, k, v, am, ah);

    gemm_mma<0><<<dim3(NE / 128, (NB * NS) / 128), 128, GT_TOTAL>>>(
        ah, woh, out, nullptr, nullptr);
}

// round 13
// speedup vs baseline: 7.4857x; 3.2042x over previous
#include <cuda_runtime.h>
#include <cuda_fp16.h>
#include <cstdint>
#include <cstring>

#define NB 4
#define NS 2048
#define NE 1024
#define NH 16
#define ND 64

// ======================= scratch (allocation-free) =========================
__device__ __half g_qh[(size_t)NB * NH * NS * ND];
__device__ __half g_kh[(size_t)NB * NH * NS * ND];
__device__ __half g_vh[(size_t)NB * NH * NS * ND];
__device__ __half g_xh[(size_t)NB * NS * NE];
__device__ __half g_ah[(size_t)NB * NS * NE];
__device__ __half g_wqkv[(size_t)3 * NE * NE];  // wq | wk | wv rows
__device__ __half g_woh[(size_t)NE * NE];

// ======================= warp-level MMA helpers ============================
__device__ __forceinline__ uint32_t smem_u32(const void* p) {
    uint32_t a;
    asm("{ .reg .u64 t; cvta.to.shared.u64 t, %1; cvt.u32.u64 %0, t; }"
        : "=r"(a) : "l"(p));
    return a;
}
__device__ __forceinline__ uint32_t h2_u32(__half2 h) {
    uint32_t u;
    memcpy(&u, &h, 4);
    return u;
}
__device__ __forceinline__ void ldm_x4(uint32_t addr, uint32_t* r) {
    asm volatile("ldmatrix.sync.aligned.m8n8.x4.shared.b16 {%0,%1,%2,%3}, [%4];"
                 : "=r"(r[0]), "=r"(r[1]), "=r"(r[2]), "=r"(r[3]) : "r"(addr));
}
__device__ __forceinline__ void ldm_x4_t(uint32_t addr, uint32_t* r) {
    asm volatile("ldmatrix.sync.aligned.m8n8.x4.trans.shared.b16 {%0,%1,%2,%3}, [%4];"
                 : "=r"(r[0]), "=r"(r[1]), "=r"(r[2]), "=r"(r[3]) : "r"(addr));
}
__device__ __forceinline__ void mma_f16(float* d, const uint32_t* a,
                                        const uint32_t* b) {
    asm volatile(
        "mma.sync.aligned.m16n8k16.row.col.f32.f16.f16.f32 "
        "{%0,%1,%2,%3}, {%4,%5,%6,%7}, {%8,%9}, {%0,%1,%2,%3};"
        : "+f"(d[0]), "+f"(d[1]), "+f"(d[2]), "+f"(d[3])
        : "r"(a[0]), "r"(a[1]), "r"(a[2]), "r"(a[3]), "r"(b[0]), "r"(b[1]));
}
#define CP_ASYNC16(dst, src)                                                   \
    asm volatile("cp.async.ca.shared.global [%0], [%1], 16;"                   \
                 :: "r"(dst), "l"(src) : "memory")
#define CP_COMMIT() asm volatile("cp.async.commit_group;" ::: "memory")
#define CP_WAIT1()  asm volatile("cp.async.wait_group 1;" ::: "memory")
#define CP_WAIT0()  asm volatile("cp.async.wait_group 0;" ::: "memory")

// ======================= conversion kernel =================================
__global__ void __launch_bounds__(256)
cvt_hi(const float* __restrict__ src, __half* __restrict__ hi, int n4) {
    int i = blockIdx.x * 256 + threadIdx.x;
    if (i >= n4) return;
    float4 v = reinterpret_cast<const float4*>(src)[i];
    __half2 p0 = __floats2half2_rn(v.x, v.y);
    __half2 p1 = __floats2half2_rn(v.z, v.w);
    reinterpret_cast<__half2*>(hi)[2 * i]     = p0;
    reinterpret_cast<__half2*>(hi)[2 * i + 1] = p1;
}

// ======================= fp16 1-pass GEMM via mma.sync =====================
// CTA 128x128, 4 warps (2m x 2n), warp tile 64x64, K-chunk 32, 3-stage pipe.
// SCATTER=1: fused QKV -> half outputs [B,H,S,D]; Q pre-scaled by 0.125.
// SCATTER=0: float row-major [M,1024].
#define GT_STRIDE 40
#define GT_TILE_B (128 * GT_STRIDE * 2)
#define GT_STAGE_B (2 * GT_TILE_B)
#define GT_TOTAL (3 * GT_STAGE_B)

template <int SCATTER>
__global__ void __launch_bounds__(128, 2)
gemm_mma(const __half* __restrict__ Ah, const __half* __restrict__ Bh,
         void* __restrict__ C0, void* __restrict__ C1, void* __restrict__ C2) {
    extern __shared__ __align__(128) char smem[];
    const uint32_t sb = smem_u32(smem);
    const int tid = threadIdx.x;
    const int wid = tid >> 5, lane = tid & 31;
    const int wm = wid & 1, wn = wid >> 1;
    const size_t m0 = (size_t)blockIdx.y * 128;
    const size_t n0 = (size_t)blockIdx.x * 128;

    auto issue_chunk = [&](int c, int buf) {
        const int kofs = c * 32;
        const uint32_t base = sb + buf * GT_STAGE_B;
#pragma unroll
        for (int it = 0; it < 8; it++) {
            const int t = it >> 2;
            const int s = tid + (it & 3) * 128;
            const int r = s >> 2;
            const int g = s & 3;
            const size_t row = (t == 0 ? m0 : n0) + r;
            const __half* gsrc = (t == 0 ? Ah : Bh) + row * NE + kofs + g * 8;
            const uint32_t dst = base + t * GT_TILE_B + r * (GT_STRIDE * 2) + g * 16;
            CP_ASYNC16(dst, gsrc);
        }
        CP_COMMIT();
    };

    float acc[4][8][4];
#pragma unroll
    for (int mi = 0; mi < 4; mi++)
#pragma unroll
        for (int nj = 0; nj < 8; nj++)
#pragma unroll
            for (int e = 0; e < 4; e++) acc[mi][nj][e] = 0.f;

    const int a_row = wm * 64 + (lane & 15);
    const int a_kb  = (lane >> 4) * 16;
    const int b_row = wn * 64 + (lane >> 4) * 8 + (lane & 7);
    const int b_kb  = ((lane >> 3) & 1) * 16;

    issue_chunk(0, 0);
    issue_chunk(1, 1);
    for (int c = 0; c < 32; c++) {
        const int buf = c % 3;
        if (c < 31) CP_WAIT1(); else CP_WAIT0();
        __syncthreads();
        if (c + 2 < 32) issue_chunk(c + 2, (c + 2) % 3);

        const uint32_t ahb = sb + buf * GT_STAGE_B;
        const uint32_t bhb = ahb + GT_TILE_B;

#pragma unroll
        for (int kk = 0; kk < 2; kk++) {
            const int kbyte = kk * 32;
            uint32_t afh[4][4], bfh[4][4];
#pragma unroll
            for (int mi = 0; mi < 4; mi++)
                ldm_x4(ahb + (a_row + mi * 16) * (GT_STRIDE * 2) + kbyte + a_kb,
                       afh[mi]);
#pragma unroll
            for (int j = 0; j < 4; j++)
                ldm_x4(bhb + (b_row + j * 16) * (GT_STRIDE * 2) + kbyte + b_kb,
                       bfh[j]);
#pragma unroll
            for (int mi = 0; mi < 4; mi++)
#pragma unroll
                for (int j = 0; j < 4; j++) {
                    mma_f16(acc[mi][2 * j],     afh[mi], bfh[j]);
                    mma_f16(acc[mi][2 * j + 1], afh[mi], bfh[j] + 2);
                }
        }
        __syncthreads();
    }

    // ---- epilogue ----
    const int row_in = lane >> 2;
    const int col2 = 2 * (lane & 3);
    __half* hbase = nullptr;
    float qscale = 1.f;
    size_t hh = 0;
    if (SCATTER) {
        const size_t nglob = n0 + wn * 64;
        const int tsel = (int)(nglob >> 10);
        hbase = (__half*)(tsel == 0 ? C0 : (tsel == 1 ? C1 : C2));
        qscale = (tsel == 0) ? 0.125f : 1.0f;
        hh = (nglob & 1023) >> 6;
    }
#pragma unroll
    for (int mi = 0; mi < 4; mi++) {
#pragma unroll
        for (int h8 = 0; h8 < 2; h8++) {
            const size_t m = m0 + wm * 64 + mi * 16 + row_in + h8 * 8;
            if (SCATTER == 0) {
                float* dst = (float*)C0 + m * NE + n0 + wn * 64;
#pragma unroll
                for (int nj = 0; nj < 8; nj++) {
                    float2 v = h8 ? make_float2(acc[mi][nj][2], acc[mi][nj][3])
                                  : make_float2(acc[mi][nj][0], acc[mi][nj][1]);
                    *reinterpret_cast<float2*>(dst + nj * 8 + col2) = v;
                }
            } else {
                const size_t bbi = m / NS, ss = m % NS;
                __half* dst = hbase + ((bbi * NH + hh) * NS + ss) * ND;
#pragma unroll
                for (int nj = 0; nj < 8; nj++) {
                    __half2 v = h8 ? __floats2half2_rn(acc[mi][nj][2] * qscale,
                                                       acc[mi][nj][3] * qscale)
                                   : __floats2half2_rn(acc[mi][nj][0] * qscale,
                                                       acc[mi][nj][1] * qscale);
                    *reinterpret_cast<__half2*>(dst + nj * 8 + col2) = v;
                }
            }
        }
    }
}

// ======================= fp16 tensor-core flash attention ==================
// CTA: 128 q-rows x kv-tiles of 64; 4 warps, each 32 q-rows.
// Q (pre-scaled by 0.125) resident in smem; K/V double-buffered cp.async.
#define ASH 144                       // smem row stride in bytes (72 halves)
#define AQ_OFF 0                      // Q: 128 * 144 = 18432 B
#define AKV_OFF 18432                 // 2 stages of (K 9216 + V 9216)
#define AKV_STAGE 18432
#define AAM_OFF (18432 + 2 * 18432)   // 55296: 2 x 64 ints
#define ATTN_SMEM (55296 + 512)

__global__ void __launch_bounds__(128, 2)
attn_mma(const __half* __restrict__ Qg, const __half* __restrict__ Kg,
         const __half* __restrict__ Vg, const int* __restrict__ amask,
         __half* __restrict__ Oh) {
    extern __shared__ __align__(128) char smem[];
    const uint32_t sb = smem_u32(smem);
    int* s_am = reinterpret_cast<int*>(smem + AAM_OFF);

    const int tid = threadIdx.x;
    const int wid = tid >> 5, lane = tid & 31;
    const int qt = blockIdx.x;
    const int q0 = qt * 128;
    const int bh = blockIdx.y;
    const int b = bh / NH;
    const int h = bh % NH;

    const __half* qg = Qg + (size_t)bh * NS * ND;
    const __half* kg = Kg + (size_t)bh * NS * ND;
    const __half* vg = Vg + (size_t)bh * NS * ND;

    // Q tile -> smem (128 rows x 128 B)
#pragma unroll
    for (int it = 0; it < 8; it++) {
        int s = tid + it * 128;
        int r = s >> 3, g = s & 7;
        uint4 v = *reinterpret_cast<const uint4*>(qg + (size_t)(q0 + r) * ND + g * 8);
        *reinterpret_cast<uint4*>(smem + AQ_OFF + r * ASH + g * 16) = v;
    }

    auto issue_kv = [&](int kt_, int bf) {
        const int k0_ = kt_ * 64;
        const uint32_t base = sb + AKV_OFF + bf * AKV_STAGE;
#pragma unroll
        for (int it = 0; it < 8; it++) {
            const int hs = it >> 2;                 // 0=K, 1=V
            const int s = tid + (it & 3) * 128;     // 0..511
            const int r = s >> 3, g = s & 7;
            const __half* src = (hs ? vg : kg) + (size_t)(k0_ + r) * ND + g * 8;
            CP_ASYNC16(base + hs * 9216 + r * ASH + g * 16, src);
        }
        CP_COMMIT();
    };

    const int ntiles = 2 * qt + 2;
    issue_kv(0, 0);
    if (tid < 64) s_am[tid] = amask[b * NS + tid];

    float acco[2][8][4];
    float m_[2][2], l_[2][2];
#pragma unroll
    for (int mi = 0; mi < 2; mi++) {
        m_[mi][0] = m_[mi][1] = -1e30f;
        l_[mi][0] = l_[mi][1] = 0.f;
#pragma unroll
        for (int nj = 0; nj < 8; nj++)
#pragma unroll
            for (int e = 0; e < 4; e++) acco[mi][nj][e] = 0.f;
    }

    const int qrow0 = q0 + wid * 32;

    for (int kt = 0; kt < ntiles; kt++) {
        const int buf = kt & 1;
        const int k0 = kt * 64;
        const bool pre = (kt + 1 < ntiles);
        int amreg = 0;
        if (pre && tid < 64) amreg = amask[b * NS + (kt + 1) * 64 + tid];

        __syncthreads();                 // prior tile's readers done with buf^1
        if (pre) {
            issue_kv(kt + 1, buf ^ 1);
            if (tid < 64) s_am[(buf ^ 1) * 64 + tid] = amreg;
            CP_WAIT1();
        } else {
            CP_WAIT0();
        }
        __syncthreads();                 // tile kt (K/V + amask) visible

        // pad-mask bits for this thread's 16 columns
        uint32_t pm = 0;
#pragma unroll
        for (int jj = 0; jj < 16; jj++) {
            int c = 8 * (jj >> 1) + 2 * (lane & 3) + (jj & 1);
            pm |= (uint32_t)(s_am[buf * 64 + c] != 0) << jj;
        }

        const uint32_t kb = sb + AKV_OFF + buf * AKV_STAGE;
        const uint32_t vb = kb + 9216;
        const uint32_t qb = sb + AQ_OFF;

        // ---- S = Q K^T (Q pre-scaled) ----
        float sacc[2][8][4];
#pragma unroll
        for (int mi = 0; mi < 2; mi++)
#pragma unroll
            for (int nj = 0; nj < 8; nj++)
#pragma unroll
                for (int e = 0; e < 4; e++) sacc[mi][nj][e] = 0.f;

#pragma unroll
        for (int t = 0; t < 4; t++) {
            uint32_t af[2][4], bf[4][4];
#pragma unroll
            for (int mi = 0; mi < 2; mi++)
                ldm_x4(qb + (wid * 32 + mi * 16 + (lane & 15)) * ASH +
                           (lane >> 4) * 16 + t * 32, af[mi]);
#pragma unroll
            for (int j = 0; j < 4; j++)
                ldm_x4(kb + (j * 16 + (lane >> 4) * 8 + (lane & 7)) * ASH +
                           ((lane >> 3) & 1) * 16 + t * 32, bf[j]);
#pragma unroll
            for (int mi = 0; mi < 2; mi++)
#pragma unroll
                for (int j = 0; j < 4; j++) {
                    mma_f16(sacc[mi][2 * j],     af[mi], bf[j]);
                    mma_f16(sacc[mi][2 * j + 1], af[mi], bf[j] + 2);
                }
        }

        // ---- mask ----
#pragma unroll
        for (int mi = 0; mi < 2; mi++)
#pragma unroll
            for (int nj = 0; nj < 8; nj++)
#pragma unroll
                for (int e = 0; e < 4; e++) {
                    int qi = qrow0 + mi * 16 + (lane >> 2) + (e >> 1) * 8;
                    int kj = k0 + 8 * nj + 2 * (lane & 3) + (e & 1);
                    bool bad = (kj > qi) || !((pm >> (2 * nj + (e & 1))) & 1);
                    if (bad) sacc[mi][nj][e] = -1e30f;
                }

        // ---- online softmax; P -> fp16 A-fragments in registers ----
        uint32_t u0[2][8], u1[2][8];
#pragma unroll
        for (int mi = 0; mi < 2; mi++) {
            float mx0 = -1e30f, mx1 = -1e30f;
#pragma unroll
            for (int nj = 0; nj < 8; nj++) {
                mx0 = fmaxf(mx0, fmaxf(sacc[mi][nj][0], sacc[mi][nj][1]));
                mx1 = fmaxf(mx1, fmaxf(sacc[mi][nj][2], sacc[mi][nj][3]));
            }
            mx0 = fmaxf(mx0, __shfl_xor_sync(0xffffffffu, mx0, 1));
            mx0 = fmaxf(mx0, __shfl_xor_sync(0xffffffffu, mx0, 2));
            mx1 = fmaxf(mx1, __shfl_xor_sync(0xffffffffu, mx1, 1));
            mx1 = fmaxf(mx1, __shfl_xor_sync(0xffffffffu, mx1, 2));

            float mn0 = fmaxf(m_[mi][0], mx0);
            float mn1 = fmaxf(m_[mi][1], mx1);
            float f0 = __expf(m_[mi][0] - mn0);
            float f1 = __expf(m_[mi][1] - mn1);
            m_[mi][0] = mn0; m_[mi][1] = mn1;

            float s0 = 0.f, s1 = 0.f;
#pragma unroll
            for (int nj = 0; nj < 8; nj++) {
                float p00 = __expf(sacc[mi][nj][0] - mn0);
                float p01 = __expf(sacc[mi][nj][1] - mn0);
                float p10 = __expf(sacc[mi][nj][2] - mn1);
                float p11 = __expf(sacc[mi][nj][3] - mn1);
                s0 += p00 + p01; s1 += p10 + p11;
                u0[mi][nj] = h2_u32(__floats2half2_rn(p00, p01));
                u1[mi][nj] = h2_u32(__floats2half2_rn(p10, p11));
            }
            s0 += __shfl_xor_sync(0xffffffffu, s0, 1);
            s0 += __shfl_xor_sync(0xffffffffu, s0, 2);
            s1 += __shfl_xor_sync(0xffffffffu, s1, 1);
            s1 += __shfl_xor_sync(0xffffffffu, s1, 2);
            l_[mi][0] = l_[mi][0] * f0 + s0;
            l_[mi][1] = l_[mi][1] * f1 + s1;
#pragma unroll
            for (int nj = 0; nj < 8; nj++) {
                acco[mi][nj][0] *= f0; acco[mi][nj][1] *= f0;
                acco[mi][nj][2] *= f1; acco[mi][nj][3] *= f1;
            }
        }

        // ---- O += P V ----
#pragma unroll
        for (int t = 0; t < 4; t++) {
            uint32_t vf[4][4];
#pragma unroll
            for (int jn = 0; jn < 4; jn++)
                ldm_x4_t(vb + (t * 16 + ((lane >> 3) & 1) * 8 + (lane & 7)) * ASH +
                             jn * 32 + (lane >> 4) * 16, vf[jn]);
#pragma unroll
            for (int mi = 0; mi < 2; mi++) {
                uint32_t a[4] = {u0[mi][2 * t], u1[mi][2 * t],
                                 u0[mi][2 * t + 1], u1[mi][2 * t + 1]};
#pragma unroll
                for (int nj = 0; nj < 8; nj++)
                    mma_f16(acco[mi][nj], a, vf[nj >> 1] + (nj & 1) * 2);
            }
        }
    }

    // ---- epilogue: O /= l, fp16 into [B,S,E] ----
#pragma unroll
    for (int mi = 0; mi < 2; mi++) {
        float inv0 = 1.f / l_[mi][0];
        float inv1 = 1.f / l_[mi][1];
        int r0 = q0 + wid * 32 + mi * 16 + (lane >> 2);
        int col = h * ND + 2 * (lane & 3);
#pragma unroll
        for (int nj = 0; nj < 8; nj++) {
            __half2 o0 = __floats2half2_rn(acco[mi][nj][0] * inv0,
                                           acco[mi][nj][1] * inv0);
            __half2 o1 = __floats2half2_rn(acco[mi][nj][2] * inv1,
                                           acco[mi][nj][3] * inv1);
            *reinterpret_cast<__half2*>(Oh + (size_t)(b * NS + r0) * NE + col + 8 * nj) = o0;
            *reinterpret_cast<__half2*>(Oh + (size_t)(b * NS + r0 + 8) * NE + col + 8 * nj) = o1;
        }
    }
}

// ======================= launcher ==========================================
extern "C" void kernel_launch(void* const* d_in, const int* in_sizes, int n_in,
                              void* d_out, int out_size) {
    (void)in_sizes; (void)n_in; (void)out_size;
    const float* x  = (const float*)d_in[0];
    const int*   am = (const int*)d_in[1];
    const float* wq = (const float*)d_in[2];
    const float* wk = (const float*)d_in[3];
    const float* wv = (const float*)d_in[4];
    const float* wo = (const float*)d_in[5];
    float* out = (float*)d_out;

    __half *qh, *kh, *vh, *xh, *ah, *wqkv, *woh;
    cudaGetSymbolAddress((void**)&qh, g_qh);
    cudaGetSymbolAddress((void**)&kh, g_kh);
    cudaGetSymbolAddress((void**)&vh, g_vh);
    cudaGetSymbolAddress((void**)&xh, g_xh);
    cudaGetSymbolAddress((void**)&ah, g_ah);
    cudaGetSymbolAddress((void**)&wqkv, g_wqkv);
    cudaGetSymbolAddress((void**)&woh, g_woh);

    const int NX4 = NB * NS * NE / 4, NW4 = NE * NE / 4;
    cvt_hi<<<(NX4 + 255) / 256, 256>>>(x, xh, NX4);
    cvt_hi<<<(NW4 + 255) / 256, 256>>>(wq, wqkv, NW4);
    cvt_hi<<<(NW4 + 255) / 256, 256>>>(wk, wqkv + (size_t)NE * NE, NW4);
    cvt_hi<<<(NW4 + 255) / 256, 256>>>(wv, wqkv + (size_t)2 * NE * NE, NW4);
    cvt_hi<<<(NW4 + 255) / 256, 256>>>(wo, woh, NW4);

    cudaFuncSetAttribute(gemm_mma<0>, cudaFuncAttributeMaxDynamicSharedMemorySize, GT_TOTAL);
    cudaFuncSetAttribute(gemm_mma<1>, cudaFuncAttributeMaxDynamicSharedMemorySize, GT_TOTAL);
    cudaFuncSetAttribute(attn_mma, cudaFuncAttributeMaxDynamicSharedMemorySize, ATTN_SMEM);

    gemm_mma<1><<<dim3(3 * NE / 128, (NB * NS) / 128), 128, GT_TOTAL>>>(
        xh, wqkv, qh, kh, vh);

    attn_mma<<<dim3(NS / 128, NB * NH), 128, ATTN_SMEM>>>(qh, kh, vh, am, ah);

    gemm_mma<0><<<dim3(NE / 128, (NB * NS) / 128), 128, GT_TOTAL>>>(
        ah, woh, out, nullptr, nullptr);
}

// round 14
// speedup vs baseline: 7.7709x; 1.0381x over previous
#include <cuda_runtime.h>
#include <cuda_fp16.h>
#include <cstdint>
#include <cstring>

#define NB 4
#define NS 2048
#define NE 1024
#define NH 16
#define ND 64

// ======================= scratch (allocation-free) =========================
__device__ __half g_qh[(size_t)NB * NH * NS * ND];
__device__ __half g_kh[(size_t)NB * NH * NS * ND];
__device__ __half g_vh[(size_t)NB * NH * NS * ND];
__device__ __half g_xh[(size_t)NB * NS * NE];
__device__ __half g_ah[(size_t)NB * NS * NE];
__device__ __half g_wqkv[(size_t)3 * NE * NE];  // wq | wk | wv rows
__device__ __half g_woh[(size_t)NE * NE];

// ======================= warp-level MMA helpers ============================
__device__ __forceinline__ uint32_t smem_u32(const void* p) {
    uint32_t a;
    asm("{ .reg .u64 t; cvta.to.shared.u64 t, %1; cvt.u32.u64 %0, t; }"
        : "=r"(a) : "l"(p));
    return a;
}
__device__ __forceinline__ uint32_t h2_u32(__half2 h) {
    uint32_t u;
    memcpy(&u, &h, 4);
    return u;
}
__device__ __forceinline__ void ldm_x4(uint32_t addr, uint32_t* r) {
    asm volatile("ldmatrix.sync.aligned.m8n8.x4.shared.b16 {%0,%1,%2,%3}, [%4];"
                 : "=r"(r[0]), "=r"(r[1]), "=r"(r[2]), "=r"(r[3]) : "r"(addr));
}
__device__ __forceinline__ void ldm_x4_t(uint32_t addr, uint32_t* r) {
    asm volatile("ldmatrix.sync.aligned.m8n8.x4.trans.shared.b16 {%0,%1,%2,%3}, [%4];"
                 : "=r"(r[0]), "=r"(r[1]), "=r"(r[2]), "=r"(r[3]) : "r"(addr));
}
__device__ __forceinline__ void mma_f16(float* d, const uint32_t* a,
                                        const uint32_t* b) {
    asm volatile(
        "mma.sync.aligned.m16n8k16.row.col.f32.f16.f16.f32 "
        "{%0,%1,%2,%3}, {%4,%5,%6,%7}, {%8,%9}, {%0,%1,%2,%3};"
        : "+f"(d[0]), "+f"(d[1]), "+f"(d[2]), "+f"(d[3])
        : "r"(a[0]), "r"(a[1]), "r"(a[2]), "r"(a[3]), "r"(b[0]), "r"(b[1]));
}
#define CP_ASYNC16(dst, src)                                                   \
    asm volatile("cp.async.ca.shared.global [%0], [%1], 16;"                   \
                 :: "r"(dst), "l"(src) : "memory")
#define CP_COMMIT() asm volatile("cp.async.commit_group;" ::: "memory")
#define CP_WAIT2()  asm volatile("cp.async.wait_group 2;" ::: "memory")
#define CP_WAIT1()  asm volatile("cp.async.wait_group 1;" ::: "memory")
#define CP_WAIT0()  asm volatile("cp.async.wait_group 0;" ::: "memory")

// ======================= fused conversion kernel ===========================
// One launch converts x -> xh and wq/wk/wv -> g_wqkv, wo -> g_woh.
#define NX4 (NB * NS * NE / 4)
#define NW4 (NE * NE / 4)

__global__ void __launch_bounds__(256)
cvt_all(const float* __restrict__ x, const float* __restrict__ wq,
        const float* __restrict__ wk, const float* __restrict__ wv,
        const float* __restrict__ wo, __half* __restrict__ xh,
        __half* __restrict__ wqkv, __half* __restrict__ woh) {
    int i = blockIdx.x * 256 + threadIdx.x;
    const int total = NX4 + 4 * NW4;
    if (i >= total) return;
    const float* src;
    __half* dst;
    int j;
    if (i < NX4) {
        src = x; dst = xh; j = i;
    } else {
        int r = i - NX4;
        int t = r / NW4;
        j = r - t * NW4;
        src = (t == 0) ? wq : (t == 1) ? wk : (t == 2) ? wv : wo;
        dst = (t == 3) ? woh : wqkv + (size_t)t * NE * NE;
    }
    float4 v = reinterpret_cast<const float4*>(src)[j];
    __half2 p0 = __floats2half2_rn(v.x, v.y);
    __half2 p1 = __floats2half2_rn(v.z, v.w);
    reinterpret_cast<__half2*>(dst)[2 * j]     = p0;
    reinterpret_cast<__half2*>(dst)[2 * j + 1] = p1;
}

// ======================= fp16 1-pass GEMM via mma.sync =====================
// CTA 128x128, 4 warps (2m x 2n), warp tile 64x64, K-chunk 32, 4-stage pipe.
// SCATTER=1: fused QKV -> half outputs [B,H,S,D]; Q pre-scaled by 0.125.
// SCATTER=0: float row-major [M,1024].
#define GT_STRIDE 40
#define GT_TILE_B (128 * GT_STRIDE * 2)
#define GT_STAGE_B (2 * GT_TILE_B)
#define GT_TOTAL (4 * GT_STAGE_B)           // 81920 B, 4 stages

template <int SCATTER>
__global__ void __launch_bounds__(128, 2)
gemm_mma(const __half* __restrict__ Ah, const __half* __restrict__ Bh,
         void* __restrict__ C0, void* __restrict__ C1, void* __restrict__ C2) {
    extern __shared__ __align__(128) char smem[];
    const uint32_t sb = smem_u32(smem);
    const int tid = threadIdx.x;
    const int wid = tid >> 5, lane = tid & 31;
    const int wm = wid & 1, wn = wid >> 1;
    const size_t m0 = (size_t)blockIdx.y * 128;
    const size_t n0 = (size_t)blockIdx.x * 128;

    auto issue_chunk = [&](int c, int buf) {
        const int kofs = c * 32;
        const uint32_t base = sb + buf * GT_STAGE_B;
#pragma unroll
        for (int it = 0; it < 8; it++) {
            const int t = it >> 2;
            const int s = tid + (it & 3) * 128;
            const int r = s >> 2;
            const int g = s & 3;
            const size_t row = (t == 0 ? m0 : n0) + r;
            const __half* gsrc = (t == 0 ? Ah : Bh) + row * NE + kofs + g * 8;
            const uint32_t dst = base + t * GT_TILE_B + r * (GT_STRIDE * 2) + g * 16;
            CP_ASYNC16(dst, gsrc);
        }
        CP_COMMIT();
    };

    float acc[4][8][4];
#pragma unroll
    for (int mi = 0; mi < 4; mi++)
#pragma unroll
        for (int nj = 0; nj < 8; nj++)
#pragma unroll
            for (int e = 0; e < 4; e++) acc[mi][nj][e] = 0.f;

    const int a_row = wm * 64 + (lane & 15);
    const int a_kb  = (lane >> 4) * 16;
    const int b_row = wn * 64 + (lane >> 4) * 8 + (lane & 7);
    const int b_kb  = ((lane >> 3) & 1) * 16;

    issue_chunk(0, 0);
    issue_chunk(1, 1);
    issue_chunk(2, 2);
    for (int c = 0; c < 32; c++) {
        const int buf = c & 3;
        if (c < 30) CP_WAIT2();
        else if (c == 30) CP_WAIT1();
        else CP_WAIT0();
        __syncthreads();
        if (c + 3 < 32) issue_chunk(c + 3, (c + 3) & 3);

        const uint32_t ahb = sb + buf * GT_STAGE_B;
        const uint32_t bhb = ahb + GT_TILE_B;

#pragma unroll
        for (int kk = 0; kk < 2; kk++) {
            const int kbyte = kk * 32;
            uint32_t afh[4][4], bfh[4][4];
#pragma unroll
            for (int mi = 0; mi < 4; mi++)
                ldm_x4(ahb + (a_row + mi * 16) * (GT_STRIDE * 2) + kbyte + a_kb,
                       afh[mi]);
#pragma unroll
            for (int j = 0; j < 4; j++)
                ldm_x4(bhb + (b_row + j * 16) * (GT_STRIDE * 2) + kbyte + b_kb,
                       bfh[j]);
#pragma unroll
            for (int mi = 0; mi < 4; mi++)
#pragma unroll
                for (int j = 0; j < 4; j++) {
                    mma_f16(acc[mi][2 * j],     afh[mi], bfh[j]);
                    mma_f16(acc[mi][2 * j + 1], afh[mi], bfh[j] + 2);
                }
        }
        __syncthreads();
    }

    // ---- epilogue ----
    const int row_in = lane >> 2;
    const int col2 = 2 * (lane & 3);
    __half* hbase = nullptr;
    float qscale = 1.f;
    size_t hh = 0;
    if (SCATTER) {
        const size_t nglob = n0 + wn * 64;
        const int tsel = (int)(nglob >> 10);
        hbase = (__half*)(tsel == 0 ? C0 : (tsel == 1 ? C1 : C2));
        qscale = (tsel == 0) ? 0.125f : 1.0f;
        hh = (nglob & 1023) >> 6;
    }
#pragma unroll
    for (int mi = 0; mi < 4; mi++) {
#pragma unroll
        for (int h8 = 0; h8 < 2; h8++) {
            const size_t m = m0 + wm * 64 + mi * 16 + row_in + h8 * 8;
            if (SCATTER == 0) {
                float* dst = (float*)C0 + m * NE + n0 + wn * 64;
#pragma unroll
                for (int nj = 0; nj < 8; nj++) {
                    float2 v = h8 ? make_float2(acc[mi][nj][2], acc[mi][nj][3])
                                  : make_float2(acc[mi][nj][0], acc[mi][nj][1]);
                    *reinterpret_cast<float2*>(dst + nj * 8 + col2) = v;
                }
            } else {
                const size_t bbi = m / NS, ss = m % NS;
                __half* dst = hbase + ((bbi * NH + hh) * NS + ss) * ND;
#pragma unroll
                for (int nj = 0; nj < 8; nj++) {
                    __half2 v = h8 ? __floats2half2_rn(acc[mi][nj][2] * qscale,
                                                       acc[mi][nj][3] * qscale)
                                   : __floats2half2_rn(acc[mi][nj][0] * qscale,
                                                       acc[mi][nj][1] * qscale);
                    *reinterpret_cast<__half2*>(dst + nj * 8 + col2) = v;
                }
            }
        }
    }
}

// ======================= fp16 tensor-core flash attention ==================
// CTA: 128 q-rows; kv-outer tiles of 128 (two inner 64-col softmax passes).
// 4 warps, each 32 q-rows. Q fragments hoisted; K/V double-buffered cp.async.
#define ASH 144                        // smem row stride in bytes (72 halves)
#define AQ_OFF 0                       // Q: 128 * 144 = 18432 B
#define AKV_OFF 18432                  // 2 stages of (K 18432 + V 18432)
#define AKV_STAGE 36864
#define AAM_OFF (18432 + 2 * 36864)    // 92160: 2 x 128 ints
#define ATTN_SMEM (92160 + 1024 + 512)

__global__ void __launch_bounds__(128, 2)
attn_mma(const __half* __restrict__ Qg, const __half* __restrict__ Kg,
         const __half* __restrict__ Vg, const int* __restrict__ amask,
         __half* __restrict__ Oh) {
    extern __shared__ __align__(128) char smem[];
    const uint32_t sb = smem_u32(smem);
    int* s_am = reinterpret_cast<int*>(smem + AAM_OFF);

    const int tid = threadIdx.x;
    const int wid = tid >> 5, lane = tid & 31;
    const int qt = blockIdx.x;
    const int q0 = qt * 128;
    const int bh = blockIdx.y;
    const int b = bh / NH;
    const int h = bh % NH;

    const __half* qg = Qg + (size_t)bh * NS * ND;
    const __half* kg = Kg + (size_t)bh * NS * ND;
    const __half* vg = Vg + (size_t)bh * NS * ND;

    auto issue_kv = [&](int kt_, int bf) {
        const int k0_ = kt_ * 128;
        const uint32_t base = sb + AKV_OFF + bf * AKV_STAGE;
#pragma unroll
        for (int it = 0; it < 16; it++) {
            const int hs = it >> 3;                 // 0=K, 1=V
            const int s = tid + (it & 7) * 128;     // 0..1023
            const int r = s >> 3, g = s & 7;
            const __half* src = (hs ? vg : kg) + (size_t)(k0_ + r) * ND + g * 8;
            CP_ASYNC16(base + hs * 18432 + r * ASH + g * 16, src);
        }
        CP_COMMIT();
    };

    issue_kv(0, 0);

    // Q tile -> smem (128 rows x 128 B)
#pragma unroll
    for (int it = 0; it < 8; it++) {
        int s = tid + it * 128;
        int r = s >> 3, g = s & 7;
        uint4 v = *reinterpret_cast<const uint4*>(qg + (size_t)(q0 + r) * ND + g * 8);
        *reinterpret_cast<uint4*>(smem + AQ_OFF + r * ASH + g * 16) = v;
    }
    s_am[tid] = amask[b * NS + tid];
    __syncthreads();

    // hoisted Q fragments (constant across kv loop)
    uint32_t qf[4][2][4];
    const uint32_t qb = sb + AQ_OFF;
#pragma unroll
    for (int t = 0; t < 4; t++)
#pragma unroll
        for (int mi = 0; mi < 2; mi++)
            ldm_x4(qb + (wid * 32 + mi * 16 + (lane & 15)) * ASH +
                       (lane >> 4) * 16 + t * 32, qf[t][mi]);

    float acco[2][8][4];
    float m_[2][2], l_[2][2];
#pragma unroll
    for (int mi = 0; mi < 2; mi++) {
        m_[mi][0] = m_[mi][1] = -1e30f;
        l_[mi][0] = l_[mi][1] = 0.f;
#pragma unroll
        for (int nj = 0; nj < 8; nj++)
#pragma unroll
            for (int e = 0; e < 4; e++) acco[mi][nj][e] = 0.f;
    }

    const int qrow0 = q0 + wid * 32;
    const int ntiles = qt + 1;

    for (int kt = 0; kt < ntiles; kt++) {
        const int buf = kt & 1;
        const bool pre = (kt + 1 < ntiles);
        int amreg = pre ? amask[b * NS + (kt + 1) * 128 + tid] : 0;

        __syncthreads();                 // prior tile's readers done with buf^1
        if (pre) {
            issue_kv(kt + 1, buf ^ 1);
            s_am[(buf ^ 1) * 128 + tid] = amreg;
            CP_WAIT1();
        } else {
            CP_WAIT0();
        }
        __syncthreads();                 // tile kt (K/V + amask) visible

        const uint32_t kb0 = sb + AKV_OFF + buf * AKV_STAGE;

#pragma unroll
        for (int h2 = 0; h2 < 2; h2++) {
            const int k0 = kt * 128 + h2 * 64;
            if (k0 > qrow0 + 31) continue;   // whole warp masked: exact no-op

            const uint32_t kb = kb0 + h2 * 64 * ASH;
            const uint32_t vb = kb0 + 18432 + h2 * 64 * ASH;

            // pad-mask bits for this thread's 16 columns
            uint32_t pm = 0;
#pragma unroll
            for (int jj = 0; jj < 16; jj++) {
                int c = 8 * (jj >> 1) + 2 * (lane & 3) + (jj & 1);
                pm |= (uint32_t)(s_am[buf * 128 + h2 * 64 + c] != 0) << jj;
            }

            // ---- S = Q K^T (Q pre-scaled) ----
            float sacc[2][8][4];
#pragma unroll
            for (int mi = 0; mi < 2; mi++)
#pragma unroll
                for (int nj = 0; nj < 8; nj++)
#pragma unroll
                    for (int e = 0; e < 4; e++) sacc[mi][nj][e] = 0.f;

#pragma unroll
            for (int t = 0; t < 4; t++) {
                uint32_t bf[4][4];
#pragma unroll
                for (int j = 0; j < 4; j++)
                    ldm_x4(kb + (j * 16 + (lane >> 4) * 8 + (lane & 7)) * ASH +
                               ((lane >> 3) & 1) * 16 + t * 32, bf[j]);
#pragma unroll
                for (int mi = 0; mi < 2; mi++)
#pragma unroll
                    for (int j = 0; j < 4; j++) {
                        mma_f16(sacc[mi][2 * j],     qf[t][mi], bf[j]);
                        mma_f16(sacc[mi][2 * j + 1], qf[t][mi], bf[j] + 2);
                    }
            }

            // ---- mask ----
#pragma unroll
            for (int mi = 0; mi < 2; mi++)
#pragma unroll
                for (int nj = 0; nj < 8; nj++)
#pragma unroll
                    for (int e = 0; e < 4; e++) {
                        int qi = qrow0 + mi * 16 + (lane >> 2) + (e >> 1) * 8;
                        int kj = k0 + 8 * nj + 2 * (lane & 3) + (e & 1);
                        bool bad = (kj > qi) || !((pm >> (2 * nj + (e & 1))) & 1);
                        if (bad) sacc[mi][nj][e] = -1e30f;
                    }

            // ---- online softmax; P -> fp16 A-fragments in registers ----
            uint32_t u0[2][8], u1[2][8];
#pragma unroll
            for (int mi = 0; mi < 2; mi++) {
                float mx0 = -1e30f, mx1 = -1e30f;
#pragma unroll
                for (int nj = 0; nj < 8; nj++) {
                    mx0 = fmaxf(mx0, fmaxf(sacc[mi][nj][0], sacc[mi][nj][1]));
                    mx1 = fmaxf(mx1, fmaxf(sacc[mi][nj][2], sacc[mi][nj][3]));
                }
                mx0 = fmaxf(mx0, __shfl_xor_sync(0xffffffffu, mx0, 1));
                mx0 = fmaxf(mx0, __shfl_xor_sync(0xffffffffu, mx0, 2));
                mx1 = fmaxf(mx1, __shfl_xor_sync(0xffffffffu, mx1, 1));
                mx1 = fmaxf(mx1, __shfl_xor_sync(0xffffffffu, mx1, 2));

                float mn0 = fmaxf(m_[mi][0], mx0);
                float mn1 = fmaxf(m_[mi][1], mx1);
                float f0 = __expf(m_[mi][0] - mn0);
                float f1 = __expf(m_[mi][1] - mn1);
                m_[mi][0] = mn0; m_[mi][1] = mn1;

                float s0 = 0.f, s1 = 0.f;
#pragma unroll
                for (int nj = 0; nj < 8; nj++) {
                    float p00 = __expf(sacc[mi][nj][0] - mn0);
                    float p01 = __expf(sacc[mi][nj][1] - mn0);
                    float p10 = __expf(sacc[mi][nj][2] - mn1);
                    float p11 = __expf(sacc[mi][nj][3] - mn1);
                    s0 += p00 + p01; s1 += p10 + p11;
                    u0[mi][nj] = h2_u32(__floats2half2_rn(p00, p01));
                    u1[mi][nj] = h2_u32(__floats2half2_rn(p10, p11));
                }
                s0 += __shfl_xor_sync(0xffffffffu, s0, 1);
                s0 += __shfl_xor_sync(0xffffffffu, s0, 2);
                s1 += __shfl_xor_sync(0xffffffffu, s1, 1);
                s1 += __shfl_xor_sync(0xffffffffu, s1, 2);
                l_[mi][0] = l_[mi][0] * f0 + s0;
                l_[mi][1] = l_[mi][1] * f1 + s1;
#pragma unroll
                for (int nj = 0; nj < 8; nj++) {
                    acco[mi][nj][0] *= f0; acco[mi][nj][1] *= f0;
                    acco[mi][nj][2] *= f1; acco[mi][nj][3] *= f1;
                }
            }

            // ---- O += P V ----
#pragma unroll
            for (int t = 0; t < 4; t++) {
                uint32_t vf[4][4];
#pragma unroll
                for (int jn = 0; jn < 4; jn++)
                    ldm_x4_t(vb + (t * 16 + ((lane >> 3) & 1) * 8 + (lane & 7)) * ASH +
                                 jn * 32 + (lane >> 4) * 16, vf[jn]);
#pragma unroll
                for (int mi = 0; mi < 2; mi++) {
                    uint32_t a[4] = {u0[mi][2 * t], u1[mi][2 * t],
                                     u0[mi][2 * t + 1], u1[mi][2 * t + 1]};
#pragma unroll
                    for (int nj = 0; nj < 8; nj++)
                        mma_f16(acco[mi][nj], a, vf[nj >> 1] + (nj & 1) * 2);
                }
            }
        }
    }

    // ---- epilogue: O /= l, fp16 into [B,S,E] ----
#pragma unroll
    for (int mi = 0; mi < 2; mi++) {
        float inv0 = 1.f / l_[mi][0];
        float inv1 = 1.f / l_[mi][1];
        int r0 = q0 + wid * 32 + mi * 16 + (lane >> 2);
        int col = h * ND + 2 * (lane & 3);
#pragma unroll
        for (int nj = 0; nj < 8; nj++) {
            __half2 o0 = __floats2half2_rn(acco[mi][nj][0] * inv0,
                                           acco[mi][nj][1] * inv0);
            __half2 o1 = __floats2half2_rn(acco[mi][nj][2] * inv1,
                                           acco[mi][nj][3] * inv1);
            *reinterpret_cast<__half2*>(Oh + (size_t)(b * NS + r0) * NE + col + 8 * nj) = o0;
            *reinterpret_cast<__half2*>(Oh + (size_t)(b * NS + r0 + 8) * NE + col + 8 * nj) = o1;
        }
    }
}

// ======================= launcher ==========================================
extern "C" void kernel_launch(void* const* d_in, const int* in_sizes, int n_in,
                              void* d_out, int out_size) {
    (void)in_sizes; (void)n_in; (void)out_size;
    const float* x  = (const float*)d_in[0];
    const int*   am = (const int*)d_in[1];
    const float* wq = (const float*)d_in[2];
    const float* wk = (const float*)d_in[3];
    const float* wv = (const float*)d_in[4];
    const float* wo = (const float*)d_in[5];
    float* out = (float*)d_out;

    __half *qh, *kh, *vh, *xh, *ah, *wqkv, *woh;
    cudaGetSymbolAddress((void**)&qh, g_qh);
    cudaGetSymbolAddress((void**)&kh, g_kh);
    cudaGetSymbolAddress((void**)&vh, g_vh);
    cudaGetSymbolAddress((void**)&xh, g_xh);
    cudaGetSymbolAddress((void**)&ah, g_ah);
    cudaGetSymbolAddress((void**)&wqkv, g_wqkv);
    cudaGetSymbolAddress((void**)&woh, g_woh);

    const int total4 = NX4 + 4 * NW4;
    cvt_all<<<(total4 + 255) / 256, 256>>>(x, wq, wk, wv, wo, xh, wqkv, woh);

    cudaFuncSetAttribute(gemm_mma<0>, cudaFuncAttributeMaxDynamicSharedMemorySize, GT_TOTAL);
    cudaFuncSetAttribute(gemm_mma<1>, cudaFuncAttributeMaxDynamicSharedMemorySize, GT_TOTAL);
    cudaFuncSetAttribute(attn_mma, cudaFuncAttributeMaxDynamicSharedMemorySize, ATTN_SMEM);

    gemm_mma<1><<<dim3(3 * NE / 128, (NB * NS) / 128), 128, GT_TOTAL>>>(
        xh, wqkv, qh, kh, vh);

    attn_mma<<<dim3(NS / 128, NB * NH), 128, ATTN_SMEM>>>(qh, kh, vh, am, ah);

    gemm_mma<0><<<dim3(NE / 128, (NB * NS) / 128), 128, GT_TOTAL>>>(
        ah, woh, out, nullptr, nullptr);
}